// round 12
// baseline (speedup 1.0000x reference)
#include <cuda_runtime.h>
#include <cuda_bf16.h>
#include <math.h>
#include <stdint.h>

#define BATCH 1024
#define NMAXN 100
#define HD    768

// ---------------- scratch (no allocations allowed) ----------------
__device__ float g_sim[BATCH * 256];
__device__ float g_h  [BATCH * 1152];
__device__ float g_h1 [BATCH * 576];
__device__ unsigned g_counter;
__device__ int g_order[2 * BATCH];
// Ww in bf16 fragment layout for m16n8k16: [kt(24)][nt(16)][lane(32)][reg(4)] (uint32 = bf16x2)
__device__ __align__(16) uint32_t g_WfragB[24 * 16 * 32 * 4];
// W1 in bf16 fragment layout for m16n8k16: [kt(36)][nt(72)][lane(32)][reg(4)]
__device__ __align__(16) uint32_t g_W1fragB[36 * 72 * 32 * 4];

__device__ __forceinline__ uint32_t pack_bf2(float lo, float hi) {
    __nv_bfloat162 p = __float22bfloat162_rn(make_float2(lo, hi));
    return *(uint32_t*)&p;
}
__device__ __forceinline__ void pref_l2(const void* p) {
    asm volatile("prefetch.global.L2 [%0];" :: "l"(p));
}

__device__ __forceinline__ void mma_bf16(float* c, const uint32_t* a, uint32_t b0, uint32_t b1) {
    asm volatile(
        "mma.sync.aligned.m16n8k16.row.col.f32.bf16.bf16.f32 "
        "{%0,%1,%2,%3}, {%4,%5,%6,%7}, {%8,%9}, {%0,%1,%2,%3};"
        : "+f"(c[0]), "+f"(c[1]), "+f"(c[2]), "+f"(c[3])
        : "r"(a[0]), "r"(a[1]), "r"(a[2]), "r"(a[3]), "r"(b0), "r"(b1));
}

// ---------------------------------------------------------------------------
// prep_kernel: counter reset + Ww bf16 frags + W1 bf16 frags in ONE launch
// ---------------------------------------------------------------------------
__global__ void prep_kernel(const float* __restrict__ Ww, const float* __restrict__ W1)
{
    if (blockIdx.x == 0 && threadIdx.x == 0) g_counter = 0u;
    if (blockIdx.x < 192) {
        int idx = blockIdx.x * 256 + threadIdx.x;      // 0..49151
        int r    = idx & 3;
        int lane = (idx >> 2) & 31;
        int nt   = (idx >> 7) & 15;
        int kt   = idx >> 11;
        int g = lane >> 2, tig = lane & 3;
        int n = nt * 8 + g;
        int k = kt * 32 + ((r >> 1) << 4) + ((r & 1) << 3) + 2 * tig;
        g_WfragB[idx] = pack_bf2(Ww[k * 128 + n], Ww[(k + 1) * 128 + n]);
    } else {
        int idx = (blockIdx.x - 192) * 256 + threadIdx.x;   // 0..331775
        int r    = idx & 3;
        int lane = (idx >> 2) & 31;
        int nt   = (idx >> 7) % 72;
        int kt   = idx / 9216;
        int g = lane >> 2, tig = lane & 3;
        int n = nt * 8 + g;
        int k = kt * 32 + ((r >> 1) << 4) + ((r & 1) << 3) + 2 * tig;
        g_W1fragB[idx] = pack_bf2(W1[k * 576 + n], W1[(k + 1) * 576 + n]);
    }
}

// ---------------------------------------------------------------------------
// sort_kernel: counting sort of 2048 items by descending len -> g_order (LPT)
// single block, 256 threads
// ---------------------------------------------------------------------------
__global__ void sort_kernel(const int* __restrict__ len1, const int* __restrict__ len2)
{
    __shared__ int hist[101];
    __shared__ int offs[101];
    const int tid = threadIdx.x;
    if (tid < 101) hist[tid] = 0;
    __syncthreads();
    for (int i = tid; i < 2 * BATCH; i += 256) {
        int b = i >> 1, s = i & 1;
        int L = s ? len2[b] : len1[b];
        if (L < 1) L = 1; if (L > NMAXN) L = NMAXN;
        atomicAdd(&hist[L], 1);
    }
    __syncthreads();
    if (tid == 0) {
        int acc = 0;
        for (int L = NMAXN; L >= 1; --L) { offs[L] = acc; acc += hist[L]; }
    }
    __syncthreads();
    for (int i = tid; i < 2 * BATCH; i += 256) {
        int b = i >> 1, s = i & 1;
        int L = s ? len2[b] : len1[b];
        if (L < 1) L = 1; if (L > NMAXN) L = NMAXN;
        int pos = atomicAdd(&offs[L], 1);
        g_order[pos] = i;
    }
}

// ---------------------------------------------------------------------------
// side_item<MC>: GEMM + epilogue for one (b,side) with mcount == MC.
// Fixed trip counts -> batched LDS + straight-line MMA issue.
// ---------------------------------------------------------------------------
template<int MC>
__device__ __forceinline__ void side_item(
    const float* const* srcp, const int* sbase, int nact,
    uint32_t* sAb, const float* sWa, const float* sBw,
    float* sWng, float* sRaw, float* sC,
    int warp, int lane, int gid, int tig, int M)
{
    float acc[MC][2][4];
#pragma unroll
    for (int mt = 0; mt < MC; ++mt)
#pragma unroll
        for (int ni = 0; ni < 2; ++ni)
#pragma unroll
            for (int q = 0; q < 4; ++q) acc[mt][ni][q] = 0.f;

    // ---- prologue ----
    float4 v[4];
#pragma unroll
    for (int i = 0; i < 4; ++i) if (i < nact) v[i] = *(const float4*)(srcp[i]);

    uint4 bq0 = *(const uint4*)(g_WfragB + ((2 * warp)     * 32 + lane) * 4);
    uint4 bq1 = *(const uint4*)(g_WfragB + ((2 * warp + 1) * 32 + lane) * 4);

#pragma unroll
    for (int i = 0; i < 4; ++i) {
        if (i < nact) {
            sAb[sbase[i]]     = pack_bf2(v[i].x, v[i].y);
            sAb[sbase[i] + 4] = pack_bf2(v[i].z, v[i].w);
        }
    }
#pragma unroll
    for (int i = 0; i < 4; ++i)
        if (i < nact) v[i] = *(const float4*)(srcp[i] + 32);
    __syncthreads();

    // ---- mainloop: 1 barrier per k-tile, fixed MC m-tiles ----
    for (int kt = 0; kt < 24; ++kt) {
        const uint32_t* cur = sAb + (kt & 1) * 1792;
        uint32_t* nxt = sAb + ((kt + 1) & 1) * 1792;

        uint4 nb0, nb1;
        if (kt < 23) {
            nb0 = *(const uint4*)(g_WfragB + (((kt + 1) * 16 + 2 * warp)     * 32 + lane) * 4);
            nb1 = *(const uint4*)(g_WfragB + (((kt + 1) * 16 + 2 * warp + 1) * 32 + lane) * 4);
#pragma unroll
            for (int i = 0; i < 4; ++i) {
                if (i < nact) {
                    nxt[sbase[i]]     = pack_bf2(v[i].x, v[i].y);
                    nxt[sbase[i] + 4] = pack_bf2(v[i].z, v[i].w);
                }
            }
            if (kt < 22) {
#pragma unroll
                for (int i = 0; i < 4; ++i)
                    if (i < nact) v[i] = *(const float4*)(srcp[i] + (kt + 2) * 32);
            }
        }

        const uint32_t* p0 = (const uint32_t*)&bq0;
        const uint32_t* p1 = (const uint32_t*)&bq1;
#pragma unroll
        for (int ks = 0; ks < 2; ++ks) {
            uint4 av[MC];
#pragma unroll
            for (int mt = 0; mt < MC; ++mt)
                av[mt] = *(const uint4*)(cur + ((mt * 2 + ks) * 32 + lane) * 4);
#pragma unroll
            for (int mt = 0; mt < MC; ++mt) {
                const uint32_t* a = (const uint32_t*)&av[mt];
                mma_bf16(acc[mt][0], a, p0[2 * ks], p0[2 * ks + 1]);
                mma_bf16(acc[mt][1], a, p1[2 * ks], p1[2 * ks + 1]);
            }
        }
        if (kt < 23) { bq0 = nb0; bq1 = nb1; }
        __syncthreads();
    }

    // ---- epilogue: + bw -> sWng scatter, fused attention dots via atomics ----
#pragma unroll
    for (int mt = 0; mt < MC; ++mt) {
        int r0 = mt * 16 + gid, r1 = r0 + 8;
        float pr0 = 0.f, pr1 = 0.f;
#pragma unroll
        for (int ni = 0; ni < 2; ++ni) {
            int cc = (2 * warp + ni) * 8 + tig * 2;
            float wa0n = sWa[128 + cc], wa1n = sWa[128 + cc + 1];
            if (r0 < M) {
                float2 o = { acc[mt][ni][0] + sBw[cc], acc[mt][ni][1] + sBw[cc + 1] };
                *(float2*)(sWng + r0 * 132 + cc) = o;
                if (r0 == 0)
                    pr0 += acc[mt][ni][0] * sWa[cc] + acc[mt][ni][1] * sWa[cc + 1];
                else
                    pr0 += acc[mt][ni][0] * wa0n + acc[mt][ni][1] * wa1n;
            }
            if (r1 < M) {
                float2 o = { acc[mt][ni][2] + sBw[cc], acc[mt][ni][3] + sBw[cc + 1] };
                *(float2*)(sWng + r1 * 132 + cc) = o;
                pr1 += acc[mt][ni][2] * wa0n + acc[mt][ni][3] * wa1n;
            }
        }
        pr0 += __shfl_xor_sync(0xffffffffu, pr0, 1);
        pr0 += __shfl_xor_sync(0xffffffffu, pr0, 2);
        pr1 += __shfl_xor_sync(0xffffffffu, pr1, 1);
        pr1 += __shfl_xor_sync(0xffffffffu, pr1, 2);
        if (tig == 0) {
            if (r0 < M) {
                if (r0 == 0) atomicAdd(sC, pr0);
                else         atomicAdd(&sRaw[r0 - 1], pr0);
            }
            if (r1 < M) atomicAdd(&sRaw[r1 - 1], pr1);
        }
    }
}

// ---------------------------------------------------------------------------
// side_kernel: persistent; per (b,side): bf16 MMA [node;neigh]@Ww, attention
// grid 296, block 256 (8 warps), dyn smem 71520 B; LPT order via g_order
// ---------------------------------------------------------------------------
__global__ void __launch_bounds__(256, 2) side_kernel(
    const float* __restrict__ node1, const float* __restrict__ node2,
    const float* __restrict__ neigh1, const float* __restrict__ neigh2,
    const float* __restrict__ dist1, const float* __restrict__ dist2,
    const int* __restrict__ len1, const int* __restrict__ len2,
    const float* __restrict__ bw,
    const float* __restrict__ Wa, const float* __restrict__ ba,
    const float* __restrict__ Wdb, const float* __restrict__ bdb)
{
    extern __shared__ float sm[];
    uint32_t* sAb = (uint32_t*)sm;       // 2 x 1792 u32
    float* sWng = sm + 3584;             // 101 rows x stride 132 = 13332 (row0 = wn)
    float* sWa  = sWng + 13332;          // 256
    float* sBw  = sWa + 256;             // 128
    float* sDist= sBw + 128;             // 104
    float* sRaw = sDist + 104;           // 104
    float* sAtt = sRaw + 104;            // 104
    float* sC   = sAtt + 104;            // 8
    float* sDot = sC + 8;                // 2
    float* sPart= sDot + 2;              // 256
    __shared__ int sIdx;

    const int tid  = threadIdx.x;
    const int warp = tid >> 5, lane = tid & 31;
    const int gid  = lane >> 2, tig = lane & 3;

    sWa[tid] = Wa[tid];
    if (tid < 128) sBw[tid] = bw[tid];
    __syncthreads();
    if (warp == 0) {
        float s0 = 0.f, s1 = 0.f;
#pragma unroll
        for (int q = 0; q < 4; ++q) {
            s0 += sBw[lane + 32 * q] * sWa[lane + 32 * q];
            s1 += sBw[lane + 32 * q] * sWa[128 + lane + 32 * q];
        }
#pragma unroll
        for (int o = 16; o > 0; o >>= 1) {
            s0 += __shfl_xor_sync(0xffffffffu, s0, o);
            s1 += __shfl_xor_sync(0xffffffffu, s1, o);
        }
        if (lane == 0) { sDot[0] = s0; sDot[1] = s1; }
    }

    const float bav = ba[0], wdbv = Wdb[0], bdbv = bdb[0];

    while (true) {
        __syncthreads();
        if (tid == 0) sIdx = (int)atomicAdd(&g_counter, 1u);
        __syncthreads();
        const int qidx = sIdx;
        if (qidx >= 2 * BATCH) break;
        const int item = g_order[qidx];
        const int b = item >> 1, side = item & 1;

        const float* node  = side ? node2  : node1;
        const float* neigh = side ? neigh2 : neigh1;
        const float* dist  = side ? dist2  : dist1;
        int len = side ? len2[b] : len1[b];
        if (len < 1) len = 1; if (len > NMAXN) len = NMAXN;
        const int M = len + 1;
        const int mcount = (M + 15) >> 4;

        if (tid < NMAXN) { sDist[tid] = dist[(size_t)b * NMAXN + tid]; sRaw[tid] = 0.f; }
        if (tid == 128) sC[0] = 0.f;

        const float* nodeRow   = node  + (size_t)b * HD;
        const float* neighBase = neigh + (size_t)b * NMAXN * HD;

        // L2 prefetch of the whole item (neigh block is contiguous)
        {
            const char* pnb = (const char*)neighBase;
            const int pbytes = len * (HD * 4);
            for (int off = tid * 128; off < pbytes; off += 256 * 128) pref_l2(pnb + off);
            if (tid < 24) pref_l2((const char*)nodeRow + tid * 128);
        }

        int nact = 0;
        const float* srcp[4];
        int sbase[4];
#pragma unroll
        for (int i = 0; i < 4; ++i) {
            int f = tid + i * 256;
            if (f < M * 8) {
                int r = f >> 3, j = f & 7;
                int mt = r >> 4, r16 = r & 15, g8 = r16 & 7, hib = r16 >> 3;
                int ks = j >> 2, half = (j >> 1) & 1, tg = (j & 1) * 2;
                srcp[i]  = (r == 0 ? nodeRow : neighBase + (size_t)(r - 1) * HD) + j * 4;
                sbase[i] = ((mt * 2 + ks) * 32 + g8 * 4 + tg) * 4 + half * 2 + hib;
                nact = i + 1;
            }
        }

        switch (mcount) {
        case 1: side_item<1>(srcp, sbase, nact, sAb, sWa, sBw, sWng, sRaw, sC, warp, lane, gid, tig, M); break;
        case 2: side_item<2>(srcp, sbase, nact, sAb, sWa, sBw, sWng, sRaw, sC, warp, lane, gid, tig, M); break;
        case 3: side_item<3>(srcp, sbase, nact, sAb, sWa, sBw, sWng, sRaw, sC, warp, lane, gid, tig, M); break;
        case 4: side_item<4>(srcp, sbase, nact, sAb, sWa, sBw, sWng, sRaw, sC, warp, lane, gid, tig, M); break;
        case 5: side_item<5>(srcp, sbase, nact, sAb, sWa, sBw, sWng, sRaw, sC, warp, lane, gid, tig, M); break;
        case 6: side_item<6>(srcp, sbase, nact, sAb, sWa, sBw, sWng, sRaw, sC, warp, lane, gid, tig, M); break;
        default: side_item<7>(srcp, sbase, nact, sAb, sWa, sBw, sWng, sRaw, sC, warp, lane, gid, tig, M); break;
        }
        __syncthreads();

        // warp 0: leaky_relu + dist bias, masked softmax
        if (warp == 0) {
            float cst = sC[0] + sDot[0] + sDot[1] + bav;
            float sc[4], ev[4];
            float mx = -3.4e38f;
#pragma unroll
            for (int q = 0; q < 4; ++q) {
                int n = lane + 32 * q;
                float vv = -3.4e38f;
                if (n < len) {
                    float x = cst + sRaw[n];
                    x = (x > 0.f) ? x : 0.01f * x;
                    vv = x + sDist[n] * wdbv + bdbv;
                }
                sc[q] = vv; mx = fmaxf(mx, vv);
            }
#pragma unroll
            for (int o = 16; o > 0; o >>= 1) mx = fmaxf(mx, __shfl_xor_sync(0xffffffffu, mx, o));
            float s = 0.f;
#pragma unroll
            for (int q = 0; q < 4; ++q) {
                int n = lane + 32 * q;
                float e = (n < len) ? expf(sc[q] - mx) : 0.f;
                ev[q] = e; s += e;
            }
#pragma unroll
            for (int o = 16; o > 0; o >>= 1) s += __shfl_xor_sync(0xffffffffu, s, o);
            float inv = 1.f / s;
#pragma unroll
            for (int q = 0; q < 4; ++q) {
                int n = lane + 32 * q;
                if (n < NMAXN) sAtt[n] = ev[q] * inv;
            }
        }
        __syncthreads();

        // ctx: split n-range across both thread halves (all 8 warps active)
        {
            const int col = tid & 127, half = tid >> 7;
            const int nmid = len >> 1;
            const int n0 = half ? nmid : 0;
            const int n1 = half ? len : nmid;
            float c0 = 0.f, c1 = 0.f;
            int n = n0;
            for (; n + 1 < n1; n += 2) {
                c0 += sAtt[n]     * sWng[(n + 1) * 132 + col];
                c1 += sAtt[n + 1] * sWng[(n + 2) * 132 + col];
            }
            if (n < n1) c0 += sAtt[n] * sWng[(n + 1) * 132 + col];
            sPart[tid] = c0 + c1;
        }
        __syncthreads();
        if (tid < 128) {
            float ctx = sPart[tid] + sPart[tid + 128];
            g_sim[(size_t)b * 256 + side * 128 + tid] = ctx * sWng[tid];
        }
    }
}

// ---------------------------------------------------------------------------
// xbuild: xneigh = relu([sim1,sim2]) @ Wn + bn -> g_h[:,896:1152],
// plus pooled/coord into g_h[:,0:896].  grid 256 (4 rows/block)
// ---------------------------------------------------------------------------
__global__ void __launch_bounds__(256) xbuild_kernel(
    const float* __restrict__ Wn, const float* __restrict__ bn,
    const float* __restrict__ pooled, const float* __restrict__ x_coord,
    const float* __restrict__ Wc, const float* __restrict__ bc)
{
    __shared__ float sS[4 * 256];
    const int b0 = blockIdx.x * 4;
    const int tid = threadIdx.x;
#pragma unroll
    for (int r = 0; r < 4; ++r)
        sS[r * 256 + tid] = fmaxf(g_sim[(size_t)(b0 + r) * 256 + tid], 0.f);
    __syncthreads();
    float acc[4];
    const float bnv = bn[tid];
#pragma unroll
    for (int r = 0; r < 4; ++r) acc[r] = bnv;
    for (int k0 = 0; k0 < 256; k0 += 4) {
        float w0 = Wn[(k0 + 0) * 256 + tid];
        float w1 = Wn[(k0 + 1) * 256 + tid];
        float w2 = Wn[(k0 + 2) * 256 + tid];
        float w3 = Wn[(k0 + 3) * 256 + tid];
#pragma unroll
        for (int r = 0; r < 4; ++r) {
            acc[r] += sS[r * 256 + k0] * w0;
            acc[r] += sS[r * 256 + k0 + 1] * w1;
            acc[r] += sS[r * 256 + k0 + 2] * w2;
            acc[r] += sS[r * 256 + k0 + 3] * w3;
        }
    }
#pragma unroll
    for (int r = 0; r < 4; ++r) {
        int b = b0 + r;
        g_h[(size_t)b * 1152 + 896 + tid] = acc[r];
#pragma unroll
        for (int p = 0; p < 3; ++p)
            g_h[(size_t)b * 1152 + p * 256 + tid] = pooled[(size_t)b * 768 + p * 256 + tid];
        if (tid < 128) {
            g_h[(size_t)b * 1152 + 768 + tid] = x_coord[b] * Wc[tid] + bc[tid];
        }
    }
}

// ---------------------------------------------------------------------------
// head_mm: g_h1 = gelu(g_h @ W1 + b1)  bf16, grid (64,9) = 16x64 tiles
// 8-buffer ring, 4 k-tiles per barrier (9 barriers)
// ---------------------------------------------------------------------------
__global__ void __launch_bounds__(256) head_mm_kernel(const float* __restrict__ b1)
{
    __shared__ uint32_t sAb[8 * 256];

    const int tid  = threadIdx.x;
    const int warp = tid >> 5, lane = tid & 31;
    const int gid  = lane >> 2, tig = lane & 3;
    const int m0   = blockIdx.x * 16;
    const int ntg  = blockIdx.y * 8 + warp;

    {
        const char* ph = (const char*)(g_h + (size_t)m0 * 1152);
        for (int off = tid * 128; off < 16 * 1152 * 4; off += 256 * 128) pref_l2(ph + off);
    }

    const bool active = tid < 128;
    const float* srcp = g_h;
    int sbase = 0;
    if (active) {
        int r = tid >> 3, j = tid & 7;
        int g8 = (r & 15) & 7, hib = (r & 15) >> 3;
        int ks = j >> 2, half = (j >> 1) & 1, tg = (j & 1) * 2;
        srcp  = g_h + (size_t)(m0 + r) * 1152 + j * 4;
        sbase = (ks * 32 + g8 * 4 + tg) * 4 + half * 2 + hib;
    }

    float acc[4];
#pragma unroll
    for (int q = 0; q < 4; ++q) acc[q] = 0.f;

    float4 v[4];
#pragma unroll
    for (int j = 0; j < 4; ++j) v[j] = make_float4(0.f, 0.f, 0.f, 0.f);
    if (active) {
#pragma unroll
        for (int j = 0; j < 4; ++j) {
            float4 t = *(const float4*)(srcp + j * 32);
            sAb[j * 256 + sbase]     = pack_bf2(t.x, t.y);
            sAb[j * 256 + sbase + 4] = pack_bf2(t.z, t.w);
        }
#pragma unroll
        for (int j = 0; j < 4; ++j) v[j] = *(const float4*)(srcp + (4 + j) * 32);
    }
    __syncthreads();

    for (int it = 0; it < 9; ++it) {
        const int kt0 = it * 4;
        const int g   = (it & 1) * 4;

        uint4 bq[4];
#pragma unroll
        for (int j = 0; j < 4; ++j)
            bq[j] = *(const uint4*)(g_W1fragB + (((kt0 + j) * 72 + ntg) * 32 + lane) * 4);

        if (it < 8 && active) {
            const int go = ((it + 1) & 1) * 4;
#pragma unroll
            for (int j = 0; j < 4; ++j) {
                sAb[(go + j) * 256 + sbase]     = pack_bf2(v[j].x, v[j].y);
                sAb[(go + j) * 256 + sbase + 4] = pack_bf2(v[j].z, v[j].w);
            }
            if (it < 7) {
#pragma unroll
                for (int j = 0; j < 4; ++j)
                    v[j] = *(const float4*)(srcp + (kt0 + 8 + j) * 32);
            }
        }

#pragma unroll
        for (int j = 0; j < 4; ++j) {
            const uint32_t* cur = sAb + (g + j) * 256;
            const uint32_t* p = (const uint32_t*)&bq[j];
#pragma unroll
            for (int ks = 0; ks < 2; ++ks) {
                uint4 av = *(const uint4*)(cur + (ks * 32 + lane) * 4);
                mma_bf16(acc, (const uint32_t*)&av, p[2 * ks], p[2 * ks + 1]);
            }
        }
        __syncthreads();
    }

    const int cc = ntg * 8 + tig * 2;
    const float bv0 = b1[cc], bv1 = b1[cc + 1];
    {
        int r0 = m0 + gid, r1 = r0 + 8;
        float x;
        x = acc[0] + bv0; g_h1[(size_t)r0 * 576 + cc]     = x * normcdff(x);
        x = acc[1] + bv1; g_h1[(size_t)r0 * 576 + cc + 1] = x * normcdff(x);
        x = acc[2] + bv0; g_h1[(size_t)r1 * 576 + cc]     = x * normcdff(x);
        x = acc[3] + bv1; g_h1[(size_t)r1 * 576 + cc + 1] = x * normcdff(x);
    }
}

// ---------------------------------------------------------------------------
// logits: out = log_softmax(g_h1 @ W2 + b2)   grid 128, block 256
// ---------------------------------------------------------------------------
__global__ void logits_kernel(const float* __restrict__ W2, const float* __restrict__ b2,
                              float* __restrict__ out)
{
    __shared__ float sW2[1152];
    const int tid = threadIdx.x;
    const int lane = tid & 31, warp = tid >> 5;
    for (int j = tid; j < 1152; j += 256) sW2[j] = W2[j];
    __syncthreads();

    const int r = blockIdx.x * 8 + warp;
    float p0 = 0.f, p1 = 0.f;
    const float* hrow = g_h1 + (size_t)r * 576;
#pragma unroll
    for (int q = 0; q < 18; ++q) {
        int j = lane + 32 * q;
        float h = hrow[j];
        p0 += h * sW2[2 * j];
        p1 += h * sW2[2 * j + 1];
    }
#pragma unroll
    for (int o = 16; o > 0; o >>= 1) {
        p0 += __shfl_xor_sync(0xffffffffu, p0, o);
        p1 += __shfl_xor_sync(0xffffffffu, p1, o);
    }
    if (lane == 0) {
        float l0 = p0 + b2[0], l1 = p1 + b2[1];
        float m = fmaxf(l0, l1);
        float lse = m + logf(expf(l0 - m) + expf(l1 - m));
        out[(size_t)r * 2 + 0] = l0 - lse;
        out[(size_t)r * 2 + 1] = l1 - lse;
    }
}

// ---------------------------------------------------------------------------
extern "C" void kernel_launch(void* const* d_in, const int* in_sizes, int n_in,
                              void* d_out, int out_size)
{
    const float* pooled = (const float*)d_in[0];
    const float* x_coord= (const float*)d_in[1];
    const float* node1  = (const float*)d_in[2];
    const float* node2  = (const float*)d_in[3];
    const float* neigh1 = (const float*)d_in[4];
    const float* neigh2 = (const float*)d_in[5];
    const float* dist1  = (const float*)d_in[6];
    const float* dist2  = (const float*)d_in[7];
    const int*   len1   = (const int*)d_in[8];
    const int*   len2   = (const int*)d_in[9];
    const float* Ww  = (const float*)d_in[10];
    const float* bw  = (const float*)d_in[11];
    const float* Wa  = (const float*)d_in[12];
    const float* ba  = (const float*)d_in[13];
    const float* Wdb = (const float*)d_in[14];
    const float* bdb = (const float*)d_in[15];
    const float* Wn  = (const float*)d_in[16];
    const float* bn  = (const float*)d_in[17];
    const float* Wc  = (const float*)d_in[18];
    const float* bc  = (const float*)d_in[19];
    const float* W1  = (const float*)d_in[20];
    const float* b1  = (const float*)d_in[21];
    const float* W2  = (const float*)d_in[22];
    const float* b2  = (const float*)d_in[23];
    float* out = (float*)d_out;

    prep_kernel<<<1488, 256>>>(Ww, W1);
    sort_kernel<<<1, 256>>>(len1, len2);

    const int smB = 17880 * (int)sizeof(float);   // 71520 B
    cudaFuncSetAttribute(side_kernel, cudaFuncAttributeMaxDynamicSharedMemorySize, smB);
    side_kernel<<<296, 256, smB>>>(node1, node2, neigh1, neigh2,
                                   dist1, dist2, len1, len2,
                                   bw, Wa, ba, Wdb, bdb);

    xbuild_kernel<<<BATCH / 4, 256>>>(Wn, bn, pooled, x_coord, Wc, bc);

    head_mm_kernel<<<dim3(64, 9), 256>>>(b1);

    logits_kernel<<<BATCH / 8, 256>>>(W2, b2, out);
}

// round 13
// speedup vs baseline: 1.6110x; 1.6110x over previous
#include <cuda_runtime.h>
#include <cuda_bf16.h>
#include <math.h>
#include <stdint.h>

#define BATCH 1024
#define NMAXN 100
#define HD    768

// ---------------- scratch (no allocations allowed) ----------------
__device__ float g_sim[BATCH * 256];
__device__ float g_h  [BATCH * 1152];
__device__ float g_h1 [BATCH * 576];
__device__ unsigned g_counter;
__device__ int g_order[2 * BATCH];
// Ww in bf16 fragment layout for m16n8k16: [kt(24)][nt(16)][lane(32)][reg(4)] (uint32 = bf16x2)
__device__ __align__(16) uint32_t g_WfragB[24 * 16 * 32 * 4];
// W1 in bf16 fragment layout for m16n8k16: [kt(36)][nt(72)][lane(32)][reg(4)]
__device__ __align__(16) uint32_t g_W1fragB[36 * 72 * 32 * 4];

__device__ __forceinline__ uint32_t pack_bf2(float lo, float hi) {
    __nv_bfloat162 p = __float22bfloat162_rn(make_float2(lo, hi));
    return *(uint32_t*)&p;
}
__device__ __forceinline__ void pref_l2(const void* p) {
    asm volatile("prefetch.global.L2 [%0];" :: "l"(p));
}

__device__ __forceinline__ void mma_bf16(float* c, const uint32_t* a, uint32_t b0, uint32_t b1) {
    asm volatile(
        "mma.sync.aligned.m16n8k16.row.col.f32.bf16.bf16.f32 "
        "{%0,%1,%2,%3}, {%4,%5,%6,%7}, {%8,%9}, {%0,%1,%2,%3};"
        : "+f"(c[0]), "+f"(c[1]), "+f"(c[2]), "+f"(c[3])
        : "r"(a[0]), "r"(a[1]), "r"(a[2]), "r"(a[3]), "r"(b0), "r"(b1));
}

// ---------------------------------------------------------------------------
// prep_kernel: counter reset + Ww bf16 frags + W1 bf16 frags in ONE launch
// ---------------------------------------------------------------------------
__global__ void prep_kernel(const float* __restrict__ Ww, const float* __restrict__ W1)
{
    if (blockIdx.x == 0 && threadIdx.x == 0) g_counter = 0u;
    if (blockIdx.x < 192) {
        int idx = blockIdx.x * 256 + threadIdx.x;      // 0..49151
        int r    = idx & 3;
        int lane = (idx >> 2) & 31;
        int nt   = (idx >> 7) & 15;
        int kt   = idx >> 11;
        int g = lane >> 2, tig = lane & 3;
        int n = nt * 8 + g;
        int k = kt * 32 + ((r >> 1) << 4) + ((r & 1) << 3) + 2 * tig;
        g_WfragB[idx] = pack_bf2(Ww[k * 128 + n], Ww[(k + 1) * 128 + n]);
    } else {
        int idx = (blockIdx.x - 192) * 256 + threadIdx.x;   // 0..331775
        int r    = idx & 3;
        int lane = (idx >> 2) & 31;
        int nt   = (idx >> 7) % 72;
        int kt   = idx / 9216;
        int g = lane >> 2, tig = lane & 3;
        int n = nt * 8 + g;
        int k = kt * 32 + ((r >> 1) << 4) + ((r & 1) << 3) + 2 * tig;
        g_W1fragB[idx] = pack_bf2(W1[k * 576 + n], W1[(k + 1) * 576 + n]);
    }
}

// ---------------------------------------------------------------------------
// sort_kernel: counting sort of 2048 items by descending len -> g_order (LPT)
// single block, 256 threads
// ---------------------------------------------------------------------------
__global__ void sort_kernel(const int* __restrict__ len1, const int* __restrict__ len2)
{
    __shared__ int hist[101];
    __shared__ int offs[101];
    const int tid = threadIdx.x;
    if (tid < 101) hist[tid] = 0;
    __syncthreads();
    for (int i = tid; i < 2 * BATCH; i += 256) {
        int b = i >> 1, s = i & 1;
        int L = s ? len2[b] : len1[b];
        if (L < 1) L = 1; if (L > NMAXN) L = NMAXN;
        atomicAdd(&hist[L], 1);
    }
    __syncthreads();
    if (tid == 0) {
        int acc = 0;
        for (int L = NMAXN; L >= 1; --L) { offs[L] = acc; acc += hist[L]; }
    }
    __syncthreads();
    for (int i = tid; i < 2 * BATCH; i += 256) {
        int b = i >> 1, s = i & 1;
        int L = s ? len2[b] : len1[b];
        if (L < 1) L = 1; if (L > NMAXN) L = NMAXN;
        int pos = atomicAdd(&offs[L], 1);
        g_order[pos] = i;
    }
}

// ---------------------------------------------------------------------------
// side_kernel: persistent; per (b,side): bf16 MMA [node;neigh]@Ww, attention
// grid 296, block 256 (8 warps), dyn smem 71520 B  (R11 body + LPT order)
// ---------------------------------------------------------------------------
__global__ void __launch_bounds__(256, 2) side_kernel(
    const float* __restrict__ node1, const float* __restrict__ node2,
    const float* __restrict__ neigh1, const float* __restrict__ neigh2,
    const float* __restrict__ dist1, const float* __restrict__ dist2,
    const int* __restrict__ len1, const int* __restrict__ len2,
    const float* __restrict__ bw,
    const float* __restrict__ Wa, const float* __restrict__ ba,
    const float* __restrict__ Wdb, const float* __restrict__ bdb)
{
    extern __shared__ float sm[];
    uint32_t* sAb = (uint32_t*)sm;       // 2 x 1792 u32
    float* sWng = sm + 3584;             // 101 rows x stride 132 = 13332 (row0 = wn)
    float* sWa  = sWng + 13332;          // 256
    float* sBw  = sWa + 256;             // 128
    float* sDist= sBw + 128;             // 104
    float* sRaw = sDist + 104;           // 104
    float* sAtt = sRaw + 104;            // 104
    float* sC   = sAtt + 104;            // 8
    float* sDot = sC + 8;                // 2
    float* sPart= sDot + 2;              // 256
    __shared__ int sIdx;

    const int tid  = threadIdx.x;
    const int warp = tid >> 5, lane = tid & 31;
    const int gid  = lane >> 2, tig = lane & 3;

    sWa[tid] = Wa[tid];
    if (tid < 128) sBw[tid] = bw[tid];
    __syncthreads();
    // one-time: dotbw0 = bw . Wa[0:128], dotbw1 = bw . Wa[128:256]
    if (warp == 0) {
        float s0 = 0.f, s1 = 0.f;
#pragma unroll
        for (int q = 0; q < 4; ++q) {
            s0 += sBw[lane + 32 * q] * sWa[lane + 32 * q];
            s1 += sBw[lane + 32 * q] * sWa[128 + lane + 32 * q];
        }
#pragma unroll
        for (int o = 16; o > 0; o >>= 1) {
            s0 += __shfl_xor_sync(0xffffffffu, s0, o);
            s1 += __shfl_xor_sync(0xffffffffu, s1, o);
        }
        if (lane == 0) { sDot[0] = s0; sDot[1] = s1; }
    }

    const float bav = ba[0], wdbv = Wdb[0], bdbv = bdb[0];

    while (true) {
        __syncthreads();
        if (tid == 0) sIdx = (int)atomicAdd(&g_counter, 1u);
        __syncthreads();
        const int qidx = sIdx;
        if (qidx >= 2 * BATCH) break;
        const int item = g_order[qidx];
        const int b = item >> 1, side = item & 1;

        const float* node  = side ? node2  : node1;
        const float* neigh = side ? neigh2 : neigh1;
        const float* dist  = side ? dist2  : dist1;
        int len = side ? len2[b] : len1[b];
        if (len < 1) len = 1; if (len > NMAXN) len = NMAXN;
        const int M = len + 1;
        const int mcount = (M + 15) >> 4;

        if (tid < NMAXN) { sDist[tid] = dist[(size_t)b * NMAXN + tid]; sRaw[tid] = 0.f; }
        if (tid == 128) sC[0] = 0.f;

        const float* nodeRow   = node  + (size_t)b * HD;
        const float* neighBase = neigh + (size_t)b * NMAXN * HD;

        // L2 prefetch of the whole item (neigh block is contiguous)
        {
            const char* pnb = (const char*)neighBase;
            const int pbytes = len * (HD * 4);
            for (int off = tid * 128; off < pbytes; off += 256 * 128) pref_l2(pnb + off);
            if (tid < 24) pref_l2((const char*)nodeRow + tid * 128);
        }

        int nact = 0;
        const float* srcp[4];
        int sbase[4];
#pragma unroll
        for (int i = 0; i < 4; ++i) {
            int f = tid + i * 256;
            if (f < M * 8) {
                int r = f >> 3, j = f & 7;
                int mt = r >> 4, r16 = r & 15, g8 = r16 & 7, hib = r16 >> 3;
                int ks = j >> 2, half = (j >> 1) & 1, tg = (j & 1) * 2;
                srcp[i]  = (r == 0 ? nodeRow : neighBase + (size_t)(r - 1) * HD) + j * 4;
                sbase[i] = ((mt * 2 + ks) * 32 + g8 * 4 + tg) * 4 + half * 2 + hib;
                nact = i + 1;
            }
        }

        float acc[7][2][4];
#pragma unroll
        for (int mt = 0; mt < 7; ++mt)
#pragma unroll
            for (int ni = 0; ni < 2; ++ni)
#pragma unroll
                for (int q = 0; q < 4; ++q) acc[mt][ni][q] = 0.f;

        // ---- prologue ----
        float4 v[4];
#pragma unroll
        for (int i = 0; i < 4; ++i) if (i < nact) v[i] = *(const float4*)(srcp[i]);

        uint4 bq0 = *(const uint4*)(g_WfragB + ((2 * warp)     * 32 + lane) * 4);
        uint4 bq1 = *(const uint4*)(g_WfragB + ((2 * warp + 1) * 32 + lane) * 4);

#pragma unroll
        for (int i = 0; i < 4; ++i) {
            if (i < nact) {
                sAb[sbase[i]]     = pack_bf2(v[i].x, v[i].y);
                sAb[sbase[i] + 4] = pack_bf2(v[i].z, v[i].w);
            }
        }
#pragma unroll
        for (int i = 0; i < 4; ++i)
            if (i < nact) v[i] = *(const float4*)(srcp[i] + 32);
        __syncthreads();

        // ---- mainloop: 1 barrier per k-tile ----
        for (int kt = 0; kt < 24; ++kt) {
            const uint32_t* cur = sAb + (kt & 1) * 1792;
            uint32_t* nxt = sAb + ((kt + 1) & 1) * 1792;

            uint4 nb0, nb1;
            if (kt < 23) {
                nb0 = *(const uint4*)(g_WfragB + (((kt + 1) * 16 + 2 * warp)     * 32 + lane) * 4);
                nb1 = *(const uint4*)(g_WfragB + (((kt + 1) * 16 + 2 * warp + 1) * 32 + lane) * 4);
#pragma unroll
                for (int i = 0; i < 4; ++i) {
                    if (i < nact) {
                        nxt[sbase[i]]     = pack_bf2(v[i].x, v[i].y);
                        nxt[sbase[i] + 4] = pack_bf2(v[i].z, v[i].w);
                    }
                }
                if (kt < 22) {
#pragma unroll
                    for (int i = 0; i < 4; ++i)
                        if (i < nact) v[i] = *(const float4*)(srcp[i] + (kt + 2) * 32);
                }
            }

            const uint32_t* p0 = (const uint32_t*)&bq0;
            const uint32_t* p1 = (const uint32_t*)&bq1;
#pragma unroll
            for (int ks = 0; ks < 2; ++ks) {
#pragma unroll
                for (int mt = 0; mt < 7; ++mt) {
                    if (mt >= mcount) break;
                    uint4 av = *(const uint4*)(cur + ((mt * 2 + ks) * 32 + lane) * 4);
                    const uint32_t* a = (const uint32_t*)&av;
                    mma_bf16(acc[mt][0], a, p0[2 * ks], p0[2 * ks + 1]);
                    mma_bf16(acc[mt][1], a, p1[2 * ks], p1[2 * ks + 1]);
                }
            }
            if (kt < 23) { bq0 = nb0; bq1 = nb1; }
            __syncthreads();
        }

        // epilogue: + bw -> sWng scatter, AND fused attention dots via atomics
#pragma unroll
        for (int mt = 0; mt < 7; ++mt) {
            if (mt >= mcount) break;
            int r0 = mt * 16 + gid, r1 = r0 + 8;
            float pr0 = 0.f, pr1 = 0.f;
#pragma unroll
            for (int ni = 0; ni < 2; ++ni) {
                int cc = (2 * warp + ni) * 8 + tig * 2;
                float wa0n = sWa[128 + cc], wa1n = sWa[128 + cc + 1];
                if (r0 < M) {
                    float2 o = { acc[mt][ni][0] + sBw[cc], acc[mt][ni][1] + sBw[cc + 1] };
                    *(float2*)(sWng + r0 * 132 + cc) = o;
                    if (r0 == 0)
                        pr0 += acc[mt][ni][0] * sWa[cc] + acc[mt][ni][1] * sWa[cc + 1];
                    else
                        pr0 += acc[mt][ni][0] * wa0n + acc[mt][ni][1] * wa1n;
                }
                if (r1 < M) {
                    float2 o = { acc[mt][ni][2] + sBw[cc], acc[mt][ni][3] + sBw[cc + 1] };
                    *(float2*)(sWng + r1 * 132 + cc) = o;
                    pr1 += acc[mt][ni][2] * wa0n + acc[mt][ni][3] * wa1n;
                }
            }
            pr0 += __shfl_xor_sync(0xffffffffu, pr0, 1);
            pr0 += __shfl_xor_sync(0xffffffffu, pr0, 2);
            pr1 += __shfl_xor_sync(0xffffffffu, pr1, 1);
            pr1 += __shfl_xor_sync(0xffffffffu, pr1, 2);
            if (tig == 0) {
                if (r0 < M) {
                    if (r0 == 0) atomicAdd(sC, pr0);
                    else         atomicAdd(&sRaw[r0 - 1], pr0);
                }
                if (r1 < M) atomicAdd(&sRaw[r1 - 1], pr1);
            }
        }
        __syncthreads();

        // warp 0: leaky_relu + dist bias, masked softmax
        if (warp == 0) {
            float cst = sC[0] + sDot[0] + sDot[1] + bav;
            float sc[4], ev[4];
            float mx = -3.4e38f;
#pragma unroll
            for (int q = 0; q < 4; ++q) {
                int n = lane + 32 * q;
                float vv = -3.4e38f;
                if (n < len) {
                    float x = cst + sRaw[n];
                    x = (x > 0.f) ? x : 0.01f * x;
                    vv = x + sDist[n] * wdbv + bdbv;
                }
                sc[q] = vv; mx = fmaxf(mx, vv);
            }
#pragma unroll
            for (int o = 16; o > 0; o >>= 1) mx = fmaxf(mx, __shfl_xor_sync(0xffffffffu, mx, o));
            float s = 0.f;
#pragma unroll
            for (int q = 0; q < 4; ++q) {
                int n = lane + 32 * q;
                float e = (n < len) ? expf(sc[q] - mx) : 0.f;
                ev[q] = e; s += e;
            }
#pragma unroll
            for (int o = 16; o > 0; o >>= 1) s += __shfl_xor_sync(0xffffffffu, s, o);
            float inv = 1.f / s;
#pragma unroll
            for (int q = 0; q < 4; ++q) {
                int n = lane + 32 * q;
                if (n < NMAXN) sAtt[n] = ev[q] * inv;
            }
        }
        __syncthreads();

        // ctx: split n-range across both thread halves (all 8 warps active)
        {
            const int col = tid & 127, half = tid >> 7;
            const int nmid = len >> 1;
            const int n0 = half ? nmid : 0;
            const int n1 = half ? len : nmid;
            float c0 = 0.f, c1 = 0.f;
            int n = n0;
            for (; n + 1 < n1; n += 2) {
                c0 += sAtt[n]     * sWng[(n + 1) * 132 + col];
                c1 += sAtt[n + 1] * sWng[(n + 2) * 132 + col];
            }
            if (n < n1) c0 += sAtt[n] * sWng[(n + 1) * 132 + col];
            sPart[tid] = c0 + c1;
        }
        __syncthreads();
        if (tid < 128) {
            float ctx = sPart[tid] + sPart[tid + 128];
            g_sim[(size_t)b * 256 + side * 128 + tid] = ctx * sWng[tid];
        }
    }
}

// ---------------------------------------------------------------------------
// xbuild: xneigh = relu([sim1,sim2]) @ Wn + bn -> g_h[:,896:1152],
// plus pooled/coord into g_h[:,0:896].  grid 256 (4 rows/block)
// ---------------------------------------------------------------------------
__global__ void __launch_bounds__(256) xbuild_kernel(
    const float* __restrict__ Wn, const float* __restrict__ bn,
    const float* __restrict__ pooled, const float* __restrict__ x_coord,
    const float* __restrict__ Wc, const float* __restrict__ bc)
{
    __shared__ float sS[4 * 256];
    const int b0 = blockIdx.x * 4;
    const int tid = threadIdx.x;
#pragma unroll
    for (int r = 0; r < 4; ++r)
        sS[r * 256 + tid] = fmaxf(g_sim[(size_t)(b0 + r) * 256 + tid], 0.f);
    __syncthreads();
    float acc[4];
    const float bnv = bn[tid];
#pragma unroll
    for (int r = 0; r < 4; ++r) acc[r] = bnv;
    for (int k0 = 0; k0 < 256; k0 += 4) {
        float w0 = Wn[(k0 + 0) * 256 + tid];
        float w1 = Wn[(k0 + 1) * 256 + tid];
        float w2 = Wn[(k0 + 2) * 256 + tid];
        float w3 = Wn[(k0 + 3) * 256 + tid];
#pragma unroll
        for (int r = 0; r < 4; ++r) {
            acc[r] += sS[r * 256 + k0] * w0;
            acc[r] += sS[r * 256 + k0 + 1] * w1;
            acc[r] += sS[r * 256 + k0 + 2] * w2;
            acc[r] += sS[r * 256 + k0 + 3] * w3;
        }
    }
#pragma unroll
    for (int r = 0; r < 4; ++r) {
        int b = b0 + r;
        g_h[(size_t)b * 1152 + 896 + tid] = acc[r];
#pragma unroll
        for (int p = 0; p < 3; ++p)
            g_h[(size_t)b * 1152 + p * 256 + tid] = pooled[(size_t)b * 768 + p * 256 + tid];
        if (tid < 128) {
            g_h[(size_t)b * 1152 + 768 + tid] = x_coord[b] * Wc[tid] + bc[tid];
        }
    }
}

// ---------------------------------------------------------------------------
// head_mm: g_h1 = gelu(g_h @ W1 + b1)  bf16, grid (64,9) = 16x64 tiles
// 8-buffer ring, 4 k-tiles per barrier (9 barriers)
// ---------------------------------------------------------------------------
__global__ void __launch_bounds__(256) head_mm_kernel(const float* __restrict__ b1)
{
    __shared__ uint32_t sAb[8 * 256];

    const int tid  = threadIdx.x;
    const int warp = tid >> 5, lane = tid & 31;
    const int gid  = lane >> 2, tig = lane & 3;
    const int m0   = blockIdx.x * 16;
    const int ntg  = blockIdx.y * 8 + warp;

    {
        const char* ph = (const char*)(g_h + (size_t)m0 * 1152);
        for (int off = tid * 128; off < 16 * 1152 * 4; off += 256 * 128) pref_l2(ph + off);
    }

    const bool active = tid < 128;
    const float* srcp = g_h;
    int sbase = 0;
    if (active) {
        int r = tid >> 3, j = tid & 7;
        int g8 = (r & 15) & 7, hib = (r & 15) >> 3;
        int ks = j >> 2, half = (j >> 1) & 1, tg = (j & 1) * 2;
        srcp  = g_h + (size_t)(m0 + r) * 1152 + j * 4;
        sbase = (ks * 32 + g8 * 4 + tg) * 4 + half * 2 + hib;
    }

    float acc[4];
#pragma unroll
    for (int q = 0; q < 4; ++q) acc[q] = 0.f;

    float4 v[4];
#pragma unroll
    for (int j = 0; j < 4; ++j) v[j] = make_float4(0.f, 0.f, 0.f, 0.f);
    if (active) {
#pragma unroll
        for (int j = 0; j < 4; ++j) {
            float4 t = *(const float4*)(srcp + j * 32);
            sAb[j * 256 + sbase]     = pack_bf2(t.x, t.y);
            sAb[j * 256 + sbase + 4] = pack_bf2(t.z, t.w);
        }
#pragma unroll
        for (int j = 0; j < 4; ++j) v[j] = *(const float4*)(srcp + (4 + j) * 32);
    }
    __syncthreads();

    for (int it = 0; it < 9; ++it) {
        const int kt0 = it * 4;
        const int g   = (it & 1) * 4;

        uint4 bq[4];
#pragma unroll
        for (int j = 0; j < 4; ++j)
            bq[j] = *(const uint4*)(g_W1fragB + (((kt0 + j) * 72 + ntg) * 32 + lane) * 4);

        if (it < 8 && active) {
            const int go = ((it + 1) & 1) * 4;
#pragma unroll
            for (int j = 0; j < 4; ++j) {
                sAb[(go + j) * 256 + sbase]     = pack_bf2(v[j].x, v[j].y);
                sAb[(go + j) * 256 + sbase + 4] = pack_bf2(v[j].z, v[j].w);
            }
            if (it < 7) {
#pragma unroll
                for (int j = 0; j < 4; ++j)
                    v[j] = *(const float4*)(srcp + (kt0 + 8 + j) * 32);
            }
        }

#pragma unroll
        for (int j = 0; j < 4; ++j) {
            const uint32_t* cur = sAb + (g + j) * 256;
            const uint32_t* p = (const uint32_t*)&bq[j];
#pragma unroll
            for (int ks = 0; ks < 2; ++ks) {
                uint4 av = *(const uint4*)(cur + (ks * 32 + lane) * 4);
                mma_bf16(acc, (const uint32_t*)&av, p[2 * ks], p[2 * ks + 1]);
            }
        }
        __syncthreads();
    }

    const int cc = ntg * 8 + tig * 2;
    const float bv0 = b1[cc], bv1 = b1[cc + 1];
    {
        int r0 = m0 + gid, r1 = r0 + 8;
        float x;
        x = acc[0] + bv0; g_h1[(size_t)r0 * 576 + cc]     = x * normcdff(x);
        x = acc[1] + bv1; g_h1[(size_t)r0 * 576 + cc + 1] = x * normcdff(x);
        x = acc[2] + bv0; g_h1[(size_t)r1 * 576 + cc]     = x * normcdff(x);
        x = acc[3] + bv1; g_h1[(size_t)r1 * 576 + cc + 1] = x * normcdff(x);
    }
}

// ---------------------------------------------------------------------------
// logits: out = log_softmax(g_h1 @ W2 + b2)   grid 128, block 256
// ---------------------------------------------------------------------------
__global__ void logits_kernel(const float* __restrict__ W2, const float* __restrict__ b2,
                              float* __restrict__ out)
{
    __shared__ float sW2[1152];
    const int tid = threadIdx.x;
    const int lane = tid & 31, warp = tid >> 5;
    for (int j = tid; j < 1152; j += 256) sW2[j] = W2[j];
    __syncthreads();

    const int r = blockIdx.x * 8 + warp;
    float p0 = 0.f, p1 = 0.f;
    const float* hrow = g_h1 + (size_t)r * 576;
#pragma unroll
    for (int q = 0; q < 18; ++q) {
        int j = lane + 32 * q;
        float h = hrow[j];
        p0 += h * sW2[2 * j];
        p1 += h * sW2[2 * j + 1];
    }
#pragma unroll
    for (int o = 16; o > 0; o >>= 1) {
        p0 += __shfl_xor_sync(0xffffffffu, p0, o);
        p1 += __shfl_xor_sync(0xffffffffu, p1, o);
    }
    if (lane == 0) {
        float l0 = p0 + b2[0], l1 = p1 + b2[1];
        float m = fmaxf(l0, l1);
        float lse = m + logf(expf(l0 - m) + expf(l1 - m));
        out[(size_t)r * 2 + 0] = l0 - lse;
        out[(size_t)r * 2 + 1] = l1 - lse;
    }
}

// ---------------------------------------------------------------------------
extern "C" void kernel_launch(void* const* d_in, const int* in_sizes, int n_in,
                              void* d_out, int out_size)
{
    const float* pooled = (const float*)d_in[0];
    const float* x_coord= (const float*)d_in[1];
    const float* node1  = (const float*)d_in[2];
    const float* node2  = (const float*)d_in[3];
    const float* neigh1 = (const float*)d_in[4];
    const float* neigh2 = (const float*)d_in[5];
    const float* dist1  = (const float*)d_in[6];
    const float* dist2  = (const float*)d_in[7];
    const int*   len1   = (const int*)d_in[8];
    const int*   len2   = (const int*)d_in[9];
    const float* Ww  = (const float*)d_in[10];
    const float* bw  = (const float*)d_in[11];
    const float* Wa  = (const float*)d_in[12];
    const float* ba  = (const float*)d_in[13];
    const float* Wdb = (const float*)d_in[14];
    const float* bdb = (const float*)d_in[15];
    const float* Wn  = (const float*)d_in[16];
    const float* bn  = (const float*)d_in[17];
    const float* Wc  = (const float*)d_in[18];
    const float* bc  = (const float*)d_in[19];
    const float* W1  = (const float*)d_in[20];
    const float* b1  = (const float*)d_in[21];
    const float* W2  = (const float*)d_in[22];
    const float* b2  = (const float*)d_in[23];
    float* out = (float*)d_out;

    prep_kernel<<<1488, 256>>>(Ww, W1);
    sort_kernel<<<1, 256>>>(len1, len2);

    const int smB = 17880 * (int)sizeof(float);   // 71520 B
    cudaFuncSetAttribute(side_kernel, cudaFuncAttributeMaxDynamicSharedMemorySize, smB);
    side_kernel<<<296, 256, smB>>>(node1, node2, neigh1, neigh2,
                                   dist1, dist2, len1, len2,
                                   bw, Wa, ba, Wdb, bdb);

    xbuild_kernel<<<BATCH / 4, 256>>>(Wn, bn, pooled, x_coord, Wc, bc);

    head_mm_kernel<<<dim3(64, 9), 256>>>(b1);

    logits_kernel<<<BATCH / 8, 256>>>(W2, b2, out);
}

// round 14
// speedup vs baseline: 1.9174x; 1.1902x over previous
#include <cuda_runtime.h>
#include <cuda_bf16.h>
#include <math.h>
#include <stdint.h>

#define BATCH 1024
#define NMAXN 100
#define HD    768

// ---------------- scratch (no allocations allowed) ----------------
__device__ float g_sim[BATCH * 256];
__device__ float g_h  [BATCH * 1152];
__device__ float g_h1 [BATCH * 576];
__device__ unsigned g_counter;
// Ww in bf16 fragment layout for m16n8k16: [kt(24)][nt(16)][lane(32)][reg(4)] (uint32 = bf16x2)
__device__ __align__(16) uint32_t g_WfragB[24 * 16 * 32 * 4];
// W1 in bf16 fragment layout: [kt(36)][nt(72)][lane(32)][reg(4)]
__device__ __align__(16) uint32_t g_W1fragB[36 * 72 * 32 * 4];
// Wn in bf16 fragment layout: [kt(8)][nt(32)][lane(32)][reg(4)]
__device__ __align__(16) uint32_t g_WnfragB[8 * 32 * 32 * 4];

__device__ __forceinline__ uint32_t pack_bf2(float lo, float hi) {
    __nv_bfloat162 p = __float22bfloat162_rn(make_float2(lo, hi));
    return *(uint32_t*)&p;
}
__device__ __forceinline__ void pref_l2(const void* p) {
    asm volatile("prefetch.global.L2 [%0];" :: "l"(p));
}

__device__ __forceinline__ void mma_bf16(float* c, const uint32_t* a, uint32_t b0, uint32_t b1) {
    asm volatile(
        "mma.sync.aligned.m16n8k16.row.col.f32.bf16.bf16.f32 "
        "{%0,%1,%2,%3}, {%4,%5,%6,%7}, {%8,%9}, {%0,%1,%2,%3};"
        : "+f"(c[0]), "+f"(c[1]), "+f"(c[2]), "+f"(c[3])
        : "r"(a[0]), "r"(a[1]), "r"(a[2]), "r"(a[3]), "r"(b0), "r"(b1));
}

// ---------------------------------------------------------------------------
// prep_kernel: counter reset + Ww/W1/Wn bf16 frags + g_h[:,0:896] fill
// grid 5200 x 256
// ---------------------------------------------------------------------------
__global__ void prep_kernel(const float* __restrict__ Ww, const float* __restrict__ W1,
                            const float* __restrict__ Wn,
                            const float* __restrict__ pooled,
                            const float* __restrict__ x_coord,
                            const float* __restrict__ Wc, const float* __restrict__ bc)
{
    if (blockIdx.x == 0 && threadIdx.x == 0) g_counter = 0u;
    if (blockIdx.x < 192) {
        int idx = blockIdx.x * 256 + threadIdx.x;      // 0..49151
        int r    = idx & 3;
        int lane = (idx >> 2) & 31;
        int nt   = (idx >> 7) & 15;
        int kt   = idx >> 11;
        int g = lane >> 2, tig = lane & 3;
        int n = nt * 8 + g;
        int k = kt * 32 + ((r >> 1) << 4) + ((r & 1) << 3) + 2 * tig;
        g_WfragB[idx] = pack_bf2(Ww[k * 128 + n], Ww[(k + 1) * 128 + n]);
    } else if (blockIdx.x < 192 + 1296) {
        int idx = (blockIdx.x - 192) * 256 + threadIdx.x;   // 0..331775
        int r    = idx & 3;
        int lane = (idx >> 2) & 31;
        int nt   = (idx >> 7) % 72;
        int kt   = idx / 9216;
        int g = lane >> 2, tig = lane & 3;
        int n = nt * 8 + g;
        int k = kt * 32 + ((r >> 1) << 4) + ((r & 1) << 3) + 2 * tig;
        g_W1fragB[idx] = pack_bf2(W1[k * 576 + n], W1[(k + 1) * 576 + n]);
    } else if (blockIdx.x < 192 + 1296 + 128) {
        int idx = (blockIdx.x - 192 - 1296) * 256 + threadIdx.x;  // 0..32767
        int r    = idx & 3;
        int lane = (idx >> 2) & 31;
        int nt   = (idx >> 7) & 31;
        int kt   = idx >> 12;                                     // /4096
        int g = lane >> 2, tig = lane & 3;
        int n = nt * 8 + g;
        int k = kt * 32 + ((r >> 1) << 4) + ((r & 1) << 3) + 2 * tig;
        g_WnfragB[idx] = pack_bf2(Wn[k * 256 + n], Wn[(k + 1) * 256 + n]);
    } else {
        int idx = (blockIdx.x - 192 - 1296 - 128) * 256 + threadIdx.x;  // 0..917503
        int b = idx / 896, j = idx - b * 896;
        float v;
        if (j < 768) v = pooled[(size_t)b * 768 + j];
        else         v = x_coord[b] * Wc[j - 768] + bc[j - 768];
        g_h[(size_t)b * 1152 + j] = v;
    }
}

// ---------------------------------------------------------------------------
// side_kernel: persistent; per (b,side): bf16 MMA [node;neigh]@Ww, attention
// grid 296, block 256 (8 warps), dyn smem 71520 B  (exact R11 body)
// ---------------------------------------------------------------------------
__global__ void __launch_bounds__(256, 2) side_kernel(
    const float* __restrict__ node1, const float* __restrict__ node2,
    const float* __restrict__ neigh1, const float* __restrict__ neigh2,
    const float* __restrict__ dist1, const float* __restrict__ dist2,
    const int* __restrict__ len1, const int* __restrict__ len2,
    const float* __restrict__ bw,
    const float* __restrict__ Wa, const float* __restrict__ ba,
    const float* __restrict__ Wdb, const float* __restrict__ bdb)
{
    extern __shared__ float sm[];
    uint32_t* sAb = (uint32_t*)sm;       // 2 x 1792 u32
    float* sWng = sm + 3584;             // 101 rows x stride 132 = 13332 (row0 = wn)
    float* sWa  = sWng + 13332;          // 256
    float* sBw  = sWa + 256;             // 128
    float* sDist= sBw + 128;             // 104
    float* sRaw = sDist + 104;           // 104
    float* sAtt = sRaw + 104;            // 104
    float* sC   = sAtt + 104;            // 8
    float* sDot = sC + 8;                // 2
    float* sPart= sDot + 2;              // 256
    __shared__ int sIdx;

    const int tid  = threadIdx.x;
    const int warp = tid >> 5, lane = tid & 31;
    const int gid  = lane >> 2, tig = lane & 3;

    sWa[tid] = Wa[tid];
    if (tid < 128) sBw[tid] = bw[tid];
    __syncthreads();
    if (warp == 0) {
        float s0 = 0.f, s1 = 0.f;
#pragma unroll
        for (int q = 0; q < 4; ++q) {
            s0 += sBw[lane + 32 * q] * sWa[lane + 32 * q];
            s1 += sBw[lane + 32 * q] * sWa[128 + lane + 32 * q];
        }
#pragma unroll
        for (int o = 16; o > 0; o >>= 1) {
            s0 += __shfl_xor_sync(0xffffffffu, s0, o);
            s1 += __shfl_xor_sync(0xffffffffu, s1, o);
        }
        if (lane == 0) { sDot[0] = s0; sDot[1] = s1; }
    }

    const float bav = ba[0], wdbv = Wdb[0], bdbv = bdb[0];

    while (true) {
        __syncthreads();
        if (tid == 0) sIdx = (int)atomicAdd(&g_counter, 1u);
        __syncthreads();
        const int item = sIdx;
        if (item >= 2 * BATCH) break;
        const int b = item >> 1, side = item & 1;

        const float* node  = side ? node2  : node1;
        const float* neigh = side ? neigh2 : neigh1;
        const float* dist  = side ? dist2  : dist1;
        int len = side ? len2[b] : len1[b];
        if (len < 1) len = 1; if (len > NMAXN) len = NMAXN;
        const int M = len + 1;
        const int mcount = (M + 15) >> 4;

        if (tid < NMAXN) { sDist[tid] = dist[(size_t)b * NMAXN + tid]; sRaw[tid] = 0.f; }
        if (tid == 128) sC[0] = 0.f;

        const float* nodeRow   = node  + (size_t)b * HD;
        const float* neighBase = neigh + (size_t)b * NMAXN * HD;

        // L2 prefetch of the whole item (neigh block is contiguous)
        {
            const char* pnb = (const char*)neighBase;
            const int pbytes = len * (HD * 4);
            for (int off = tid * 128; off < pbytes; off += 256 * 128) pref_l2(pnb + off);
            if (tid < 24) pref_l2((const char*)nodeRow + tid * 128);
        }

        int nact = 0;
        const float* srcp[4];
        int sbase[4];
#pragma unroll
        for (int i = 0; i < 4; ++i) {
            int f = tid + i * 256;
            if (f < M * 8) {
                int r = f >> 3, j = f & 7;
                int mt = r >> 4, r16 = r & 15, g8 = r16 & 7, hib = r16 >> 3;
                int ks = j >> 2, half = (j >> 1) & 1, tg = (j & 1) * 2;
                srcp[i]  = (r == 0 ? nodeRow : neighBase + (size_t)(r - 1) * HD) + j * 4;
                sbase[i] = ((mt * 2 + ks) * 32 + g8 * 4 + tg) * 4 + half * 2 + hib;
                nact = i + 1;
            }
        }

        float acc[7][2][4];
#pragma unroll
        for (int mt = 0; mt < 7; ++mt)
#pragma unroll
            for (int ni = 0; ni < 2; ++ni)
#pragma unroll
                for (int q = 0; q < 4; ++q) acc[mt][ni][q] = 0.f;

        // ---- prologue ----
        float4 v[4];
#pragma unroll
        for (int i = 0; i < 4; ++i) if (i < nact) v[i] = *(const float4*)(srcp[i]);

        uint4 bq0 = *(const uint4*)(g_WfragB + ((2 * warp)     * 32 + lane) * 4);
        uint4 bq1 = *(const uint4*)(g_WfragB + ((2 * warp + 1) * 32 + lane) * 4);

#pragma unroll
        for (int i = 0; i < 4; ++i) {
            if (i < nact) {
                sAb[sbase[i]]     = pack_bf2(v[i].x, v[i].y);
                sAb[sbase[i] + 4] = pack_bf2(v[i].z, v[i].w);
            }
        }
#pragma unroll
        for (int i = 0; i < 4; ++i)
            if (i < nact) v[i] = *(const float4*)(srcp[i] + 32);
        __syncthreads();

        // ---- mainloop: 1 barrier per k-tile ----
        for (int kt = 0; kt < 24; ++kt) {
            const uint32_t* cur = sAb + (kt & 1) * 1792;
            uint32_t* nxt = sAb + ((kt + 1) & 1) * 1792;

            uint4 nb0, nb1;
            if (kt < 23) {
                nb0 = *(const uint4*)(g_WfragB + (((kt + 1) * 16 + 2 * warp)     * 32 + lane) * 4);
                nb1 = *(const uint4*)(g_WfragB + (((kt + 1) * 16 + 2 * warp + 1) * 32 + lane) * 4);
#pragma unroll
                for (int i = 0; i < 4; ++i) {
                    if (i < nact) {
                        nxt[sbase[i]]     = pack_bf2(v[i].x, v[i].y);
                        nxt[sbase[i] + 4] = pack_bf2(v[i].z, v[i].w);
                    }
                }
                if (kt < 22) {
#pragma unroll
                    for (int i = 0; i < 4; ++i)
                        if (i < nact) v[i] = *(const float4*)(srcp[i] + (kt + 2) * 32);
                }
            }

            const uint32_t* p0 = (const uint32_t*)&bq0;
            const uint32_t* p1 = (const uint32_t*)&bq1;
#pragma unroll
            for (int ks = 0; ks < 2; ++ks) {
#pragma unroll
                for (int mt = 0; mt < 7; ++mt) {
                    if (mt >= mcount) break;
                    uint4 av = *(const uint4*)(cur + ((mt * 2 + ks) * 32 + lane) * 4);
                    const uint32_t* a = (const uint32_t*)&av;
                    mma_bf16(acc[mt][0], a, p0[2 * ks], p0[2 * ks + 1]);
                    mma_bf16(acc[mt][1], a, p1[2 * ks], p1[2 * ks + 1]);
                }
            }
            if (kt < 23) { bq0 = nb0; bq1 = nb1; }
            __syncthreads();
        }

        // epilogue: + bw -> sWng scatter, AND fused attention dots via atomics
#pragma unroll
        for (int mt = 0; mt < 7; ++mt) {
            if (mt >= mcount) break;
            int r0 = mt * 16 + gid, r1 = r0 + 8;
            float pr0 = 0.f, pr1 = 0.f;
#pragma unroll
            for (int ni = 0; ni < 2; ++ni) {
                int cc = (2 * warp + ni) * 8 + tig * 2;
                float wa0n = sWa[128 + cc], wa1n = sWa[128 + cc + 1];
                if (r0 < M) {
                    float2 o = { acc[mt][ni][0] + sBw[cc], acc[mt][ni][1] + sBw[cc + 1] };
                    *(float2*)(sWng + r0 * 132 + cc) = o;
                    if (r0 == 0)
                        pr0 += acc[mt][ni][0] * sWa[cc] + acc[mt][ni][1] * sWa[cc + 1];
                    else
                        pr0 += acc[mt][ni][0] * wa0n + acc[mt][ni][1] * wa1n;
                }
                if (r1 < M) {
                    float2 o = { acc[mt][ni][2] + sBw[cc], acc[mt][ni][3] + sBw[cc + 1] };
                    *(float2*)(sWng + r1 * 132 + cc) = o;
                    pr1 += acc[mt][ni][2] * wa0n + acc[mt][ni][3] * wa1n;
                }
            }
            pr0 += __shfl_xor_sync(0xffffffffu, pr0, 1);
            pr0 += __shfl_xor_sync(0xffffffffu, pr0, 2);
            pr1 += __shfl_xor_sync(0xffffffffu, pr1, 1);
            pr1 += __shfl_xor_sync(0xffffffffu, pr1, 2);
            if (tig == 0) {
                if (r0 < M) {
                    if (r0 == 0) atomicAdd(sC, pr0);
                    else         atomicAdd(&sRaw[r0 - 1], pr0);
                }
                if (r1 < M) atomicAdd(&sRaw[r1 - 1], pr1);
            }
        }
        __syncthreads();

        // warp 0: leaky_relu + dist bias, masked softmax
        if (warp == 0) {
            float cst = sC[0] + sDot[0] + sDot[1] + bav;
            float sc[4], ev[4];
            float mx = -3.4e38f;
#pragma unroll
            for (int q = 0; q < 4; ++q) {
                int n = lane + 32 * q;
                float vv = -3.4e38f;
                if (n < len) {
                    float x = cst + sRaw[n];
                    x = (x > 0.f) ? x : 0.01f * x;
                    vv = x + sDist[n] * wdbv + bdbv;
                }
                sc[q] = vv; mx = fmaxf(mx, vv);
            }
#pragma unroll
            for (int o = 16; o > 0; o >>= 1) mx = fmaxf(mx, __shfl_xor_sync(0xffffffffu, mx, o));
            float s = 0.f;
#pragma unroll
            for (int q = 0; q < 4; ++q) {
                int n = lane + 32 * q;
                float e = (n < len) ? expf(sc[q] - mx) : 0.f;
                ev[q] = e; s += e;
            }
#pragma unroll
            for (int o = 16; o > 0; o >>= 1) s += __shfl_xor_sync(0xffffffffu, s, o);
            float inv = 1.f / s;
#pragma unroll
            for (int q = 0; q < 4; ++q) {
                int n = lane + 32 * q;
                if (n < NMAXN) sAtt[n] = ev[q] * inv;
            }
        }
        __syncthreads();

        // ctx: split n-range across both thread halves (all 8 warps active)
        {
            const int col = tid & 127, half = tid >> 7;
            const int nmid = len >> 1;
            const int n0 = half ? nmid : 0;
            const int n1 = half ? len : nmid;
            float c0 = 0.f, c1 = 0.f;
            int n = n0;
            for (; n + 1 < n1; n += 2) {
                c0 += sAtt[n]     * sWng[(n + 1) * 132 + col];
                c1 += sAtt[n + 1] * sWng[(n + 2) * 132 + col];
            }
            if (n < n1) c0 += sAtt[n] * sWng[(n + 1) * 132 + col];
            sPart[tid] = c0 + c1;
        }
        __syncthreads();
        if (tid < 128) {
            float ctx = sPart[tid] + sPart[tid + 128];
            g_sim[(size_t)b * 256 + side * 128 + tid] = ctx * sWng[tid];
        }
    }
}

// ---------------------------------------------------------------------------
// xneigh_mm: g_h[:,896:1152] = relu(g_sim) @ Wn + bn   bf16 MMA
// grid (64,4), block 256: 16 rows x 64 cols per block; K=256 = 8 k-tiles
// A staged once (no pipeline), 16 MMAs per warp
// ---------------------------------------------------------------------------
__global__ void __launch_bounds__(256) xneigh_mm_kernel(const float* __restrict__ bn)
{
    __shared__ uint32_t sAb[8 * 256];   // 8 k-tiles x [ks(2)][lane(32)][reg(4)]

    const int tid  = threadIdx.x;
    const int warp = tid >> 5, lane = tid & 31;
    const int gid  = lane >> 2, tig = lane & 3;
    const int m0   = blockIdx.x * 16;
    const int ntg  = blockIdx.y * 8 + warp;      // 0..31

    const bool active = tid < 128;
    if (active) {
        int r = tid >> 3, j = tid & 7;
        int g8 = (r & 15) & 7, hib = (r & 15) >> 3;
        int ks = j >> 2, half = (j >> 1) & 1, tg = (j & 1) * 2;
        const float* srcp = g_sim + (size_t)(m0 + r) * 256 + j * 4;
        int sbase = (ks * 32 + g8 * 4 + tg) * 4 + half * 2 + hib;
#pragma unroll
        for (int kt = 0; kt < 8; ++kt) {
            float4 t = *(const float4*)(srcp + kt * 32);
            t.x = fmaxf(t.x, 0.f); t.y = fmaxf(t.y, 0.f);
            t.z = fmaxf(t.z, 0.f); t.w = fmaxf(t.w, 0.f);
            sAb[kt * 256 + sbase]     = pack_bf2(t.x, t.y);
            sAb[kt * 256 + sbase + 4] = pack_bf2(t.z, t.w);
        }
    }
    __syncthreads();

    float acc[4];
#pragma unroll
    for (int q = 0; q < 4; ++q) acc[q] = 0.f;

#pragma unroll
    for (int kt = 0; kt < 8; ++kt) {
        uint4 bq = *(const uint4*)(g_WnfragB + ((kt * 32 + ntg) * 32 + lane) * 4);
        const uint32_t* p = (const uint32_t*)&bq;
        const uint32_t* cur = sAb + kt * 256;
#pragma unroll
        for (int ks = 0; ks < 2; ++ks) {
            uint4 av = *(const uint4*)(cur + (ks * 32 + lane) * 4);
            mma_bf16(acc, (const uint32_t*)&av, p[2 * ks], p[2 * ks + 1]);
        }
    }

    const int cc = ntg * 8 + tig * 2;
    const float bv0 = bn[cc], bv1 = bn[cc + 1];
    {
        int r0 = m0 + gid, r1 = r0 + 8;
        g_h[(size_t)r0 * 1152 + 896 + cc]     = acc[0] + bv0;
        g_h[(size_t)r0 * 1152 + 896 + cc + 1] = acc[1] + bv1;
        g_h[(size_t)r1 * 1152 + 896 + cc]     = acc[2] + bv0;
        g_h[(size_t)r1 * 1152 + 896 + cc + 1] = acc[3] + bv1;
    }
}

// ---------------------------------------------------------------------------
// head_mm: g_h1 = gelu(g_h @ W1 + b1)  bf16, grid (64,9) = 16x64 tiles
// 8-buffer ring, 4 k-tiles per barrier (9 barriers)
// ---------------------------------------------------------------------------
__global__ void __launch_bounds__(256) head_mm_kernel(const float* __restrict__ b1)
{
    __shared__ uint32_t sAb[8 * 256];

    const int tid  = threadIdx.x;
    const int warp = tid >> 5, lane = tid & 31;
    const int gid  = lane >> 2, tig = lane & 3;
    const int m0   = blockIdx.x * 16;
    const int ntg  = blockIdx.y * 8 + warp;

    {
        const char* ph = (const char*)(g_h + (size_t)m0 * 1152);
        for (int off = tid * 128; off < 16 * 1152 * 4; off += 256 * 128) pref_l2(ph + off);
    }

    const bool active = tid < 128;
    const float* srcp = g_h;
    int sbase = 0;
    if (active) {
        int r = tid >> 3, j = tid & 7;
        int g8 = (r & 15) & 7, hib = (r & 15) >> 3;
        int ks = j >> 2, half = (j >> 1) & 1, tg = (j & 1) * 2;
        srcp  = g_h + (size_t)(m0 + r) * 1152 + j * 4;
        sbase = (ks * 32 + g8 * 4 + tg) * 4 + half * 2 + hib;
    }

    float acc[4];
#pragma unroll
    for (int q = 0; q < 4; ++q) acc[q] = 0.f;

    float4 v[4];
#pragma unroll
    for (int j = 0; j < 4; ++j) v[j] = make_float4(0.f, 0.f, 0.f, 0.f);
    if (active) {
#pragma unroll
        for (int j = 0; j < 4; ++j) {
            float4 t = *(const float4*)(srcp + j * 32);
            sAb[j * 256 + sbase]     = pack_bf2(t.x, t.y);
            sAb[j * 256 + sbase + 4] = pack_bf2(t.z, t.w);
        }
#pragma unroll
        for (int j = 0; j < 4; ++j) v[j] = *(const float4*)(srcp + (4 + j) * 32);
    }
    __syncthreads();

    for (int it = 0; it < 9; ++it) {
        const int kt0 = it * 4;
        const int g   = (it & 1) * 4;

        uint4 bq[4];
#pragma unroll
        for (int j = 0; j < 4; ++j)
            bq[j] = *(const uint4*)(g_W1fragB + (((kt0 + j) * 72 + ntg) * 32 + lane) * 4);

        if (it < 8 && active) {
            const int go = ((it + 1) & 1) * 4;
#pragma unroll
            for (int j = 0; j < 4; ++j) {
                sAb[(go + j) * 256 + sbase]     = pack_bf2(v[j].x, v[j].y);
                sAb[(go + j) * 256 + sbase + 4] = pack_bf2(v[j].z, v[j].w);
            }
            if (it < 7) {
#pragma unroll
                for (int j = 0; j < 4; ++j)
                    v[j] = *(const float4*)(srcp + (kt0 + 8 + j) * 32);
            }
        }

#pragma unroll
        for (int j = 0; j < 4; ++j) {
            const uint32_t* cur = sAb + (g + j) * 256;
            const uint32_t* p = (const uint32_t*)&bq[j];
#pragma unroll
            for (int ks = 0; ks < 2; ++ks) {
                uint4 av = *(const uint4*)(cur + (ks * 32 + lane) * 4);
                mma_bf16(acc, (const uint32_t*)&av, p[2 * ks], p[2 * ks + 1]);
            }
        }
        __syncthreads();
    }

    const int cc = ntg * 8 + tig * 2;
    const float bv0 = b1[cc], bv1 = b1[cc + 1];
    {
        int r0 = m0 + gid, r1 = r0 + 8;
        float x;
        x = acc[0] + bv0; g_h1[(size_t)r0 * 576 + cc]     = x * normcdff(x);
        x = acc[1] + bv1; g_h1[(size_t)r0 * 576 + cc + 1] = x * normcdff(x);
        x = acc[2] + bv0; g_h1[(size_t)r1 * 576 + cc]     = x * normcdff(x);
        x = acc[3] + bv1; g_h1[(size_t)r1 * 576 + cc + 1] = x * normcdff(x);
    }
}

// ---------------------------------------------------------------------------
// logits: out = log_softmax(g_h1 @ W2 + b2)   grid 128, block 256
// ---------------------------------------------------------------------------
__global__ void logits_kernel(const float* __restrict__ W2, const float* __restrict__ b2,
                              float* __restrict__ out)
{
    __shared__ float sW2[1152];
    const int tid = threadIdx.x;
    const int lane = tid & 31, warp = tid >> 5;
    for (int j = tid; j < 1152; j += 256) sW2[j] = W2[j];
    __syncthreads();

    const int r = blockIdx.x * 8 + warp;
    float p0 = 0.f, p1 = 0.f;
    const float* hrow = g_h1 + (size_t)r * 576;
#pragma unroll
    for (int q = 0; q < 18; ++q) {
        int j = lane + 32 * q;
        float h = hrow[j];
        p0 += h * sW2[2 * j];
        p1 += h * sW2[2 * j + 1];
    }
#pragma unroll
    for (int o = 16; o > 0; o >>= 1) {
        p0 += __shfl_xor_sync(0xffffffffu, p0, o);
        p1 += __shfl_xor_sync(0xffffffffu, p1, o);
    }
    if (lane == 0) {
        float l0 = p0 + b2[0], l1 = p1 + b2[1];
        float m = fmaxf(l0, l1);
        float lse = m + logf(expf(l0 - m) + expf(l1 - m));
        out[(size_t)r * 2 + 0] = l0 - lse;
        out[(size_t)r * 2 + 1] = l1 - lse;
    }
}

// ---------------------------------------------------------------------------
extern "C" void kernel_launch(void* const* d_in, const int* in_sizes, int n_in,
                              void* d_out, int out_size)
{
    const float* pooled = (const float*)d_in[0];
    const float* x_coord= (const float*)d_in[1];
    const float* node1  = (const float*)d_in[2];
    const float* node2  = (const float*)d_in[3];
    const float* neigh1 = (const float*)d_in[4];
    const float* neigh2 = (const float*)d_in[5];
    const float* dist1  = (const float*)d_in[6];
    const float* dist2  = (const float*)d_in[7];
    const int*   len1   = (const int*)d_in[8];
    const int*   len2   = (const int*)d_in[9];
    const float* Ww  = (const float*)d_in[10];
    const float* bw  = (const float*)d_in[11];
    const float* Wa  = (const float*)d_in[12];
    const float* ba  = (const float*)d_in[13];
    const float* Wdb = (const float*)d_in[14];
    const float* bdb = (const float*)d_in[15];
    const float* Wn  = (const float*)d_in[16];
    const float* bn  = (const float*)d_in[17];
    const float* Wc  = (const float*)d_in[18];
    const float* bc  = (const float*)d_in[19];
    const float* W1  = (const float*)d_in[20];
    const float* b1  = (const float*)d_in[21];
    const float* W2  = (const float*)d_in[22];
    const float* b2  = (const float*)d_in[23];
    float* out = (float*)d_out;

    prep_kernel<<<5200, 256>>>(Ww, W1, Wn, pooled, x_coord, Wc, bc);

    const int smB = 17880 * (int)sizeof(float);   // 71520 B
    cudaFuncSetAttribute(side_kernel, cudaFuncAttributeMaxDynamicSharedMemorySize, smB);
    side_kernel<<<296, 256, smB>>>(node1, node2, neigh1, neigh2,
                                   dist1, dist2, len1, len2,
                                   bw, Wa, ba, Wdb, bdb);

    xneigh_mm_kernel<<<dim3(64, 4), 256>>>(bn);

    head_mm_kernel<<<dim3(64, 9), 256>>>(b1);

    logits_kernel<<<BATCH / 8, 256>>>(W2, b2, out);
}

// round 15
// speedup vs baseline: 2.0009x; 1.0435x over previous
#include <cuda_runtime.h>
#include <cuda_bf16.h>
#include <math.h>
#include <stdint.h>

#define BATCH 1024
#define NMAXN 100
#define HD    768

// ---------------- scratch (no allocations allowed) ----------------
__device__ float g_sim[BATCH * 256];
__device__ float g_h  [BATCH * 1152];
__device__ float g_h1 [BATCH * 576];
__device__ unsigned g_counter;
// Ww in bf16 fragment layout for m16n8k16: [kt(24)][nt(16)][lane(32)][reg(4)] (uint32 = bf16x2)
__device__ __align__(16) uint32_t g_WfragB[24 * 16 * 32 * 4];
// W1 in bf16 fragment layout: [kt(36)][nt(72)][lane(32)][reg(4)]
__device__ __align__(16) uint32_t g_W1fragB[36 * 72 * 32 * 4];
// Wn in bf16 fragment layout: [kt(8)][nt(32)][lane(32)][reg(4)]
__device__ __align__(16) uint32_t g_WnfragB[8 * 32 * 32 * 4];

__device__ __forceinline__ uint32_t pack_bf2(float lo, float hi) {
    __nv_bfloat162 p = __float22bfloat162_rn(make_float2(lo, hi));
    return *(uint32_t*)&p;
}
__device__ __forceinline__ void pref_l2(const void* p) {
    asm volatile("prefetch.global.L2 [%0];" :: "l"(p));
}

__device__ __forceinline__ void mma_bf16(float* c, const uint32_t* a, uint32_t b0, uint32_t b1) {
    asm volatile(
        "mma.sync.aligned.m16n8k16.row.col.f32.bf16.bf16.f32 "
        "{%0,%1,%2,%3}, {%4,%5,%6,%7}, {%8,%9}, {%0,%1,%2,%3};"
        : "+f"(c[0]), "+f"(c[1]), "+f"(c[2]), "+f"(c[3])
        : "r"(a[0]), "r"(a[1]), "r"(a[2]), "r"(a[3]), "r"(b0), "r"(b1));
}

// ---------------------------------------------------------------------------
// prep_kernel: counter reset + Ww/W1/Wn bf16 frags + g_h[:,0:896] fill
// grid 5200 x 256
// ---------------------------------------------------------------------------
__global__ void prep_kernel(const float* __restrict__ Ww, const float* __restrict__ W1,
                            const float* __restrict__ Wn,
                            const float* __restrict__ pooled,
                            const float* __restrict__ x_coord,
                            const float* __restrict__ Wc, const float* __restrict__ bc)
{
    if (blockIdx.x == 0 && threadIdx.x == 0) g_counter = 0u;
    if (blockIdx.x < 192) {
        int idx = blockIdx.x * 256 + threadIdx.x;      // 0..49151
        int r    = idx & 3;
        int lane = (idx >> 2) & 31;
        int nt   = (idx >> 7) & 15;
        int kt   = idx >> 11;
        int g = lane >> 2, tig = lane & 3;
        int n = nt * 8 + g;
        int k = kt * 32 + ((r >> 1) << 4) + ((r & 1) << 3) + 2 * tig;
        g_WfragB[idx] = pack_bf2(Ww[k * 128 + n], Ww[(k + 1) * 128 + n]);
    } else if (blockIdx.x < 192 + 1296) {
        int idx = (blockIdx.x - 192) * 256 + threadIdx.x;   // 0..331775
        int r    = idx & 3;
        int lane = (idx >> 2) & 31;
        int nt   = (idx >> 7) % 72;
        int kt   = idx / 9216;
        int g = lane >> 2, tig = lane & 3;
        int n = nt * 8 + g;
        int k = kt * 32 + ((r >> 1) << 4) + ((r & 1) << 3) + 2 * tig;
        g_W1fragB[idx] = pack_bf2(W1[k * 576 + n], W1[(k + 1) * 576 + n]);
    } else if (blockIdx.x < 192 + 1296 + 128) {
        int idx = (blockIdx.x - 192 - 1296) * 256 + threadIdx.x;  // 0..32767
        int r    = idx & 3;
        int lane = (idx >> 2) & 31;
        int nt   = (idx >> 7) & 31;
        int kt   = idx >> 12;                                     // /4096
        int g = lane >> 2, tig = lane & 3;
        int n = nt * 8 + g;
        int k = kt * 32 + ((r >> 1) << 4) + ((r & 1) << 3) + 2 * tig;
        g_WnfragB[idx] = pack_bf2(Wn[k * 256 + n], Wn[(k + 1) * 256 + n]);
    } else {
        int idx = (blockIdx.x - 192 - 1296 - 128) * 256 + threadIdx.x;  // 0..917503
        int b = idx / 896, j = idx - b * 896;
        float v;
        if (j < 768) v = pooled[(size_t)b * 768 + j];
        else         v = x_coord[b] * Wc[j - 768] + bc[j - 768];
        g_h[(size_t)b * 1152 + j] = v;
    }
}

// ---------------------------------------------------------------------------
// side_kernel: persistent; per (b,side): bf16 MMA [node;neigh]@Ww, attention
// grid 296, block 256 (8 warps), dyn smem 85856 B
// 4-buffer A staging, 2 k-tiles per barrier (12 barriers per item)
// ---------------------------------------------------------------------------
__global__ void __launch_bounds__(256, 2) side_kernel(
    const float* __restrict__ node1, const float* __restrict__ node2,
    const float* __restrict__ neigh1, const float* __restrict__ neigh2,
    const float* __restrict__ dist1, const float* __restrict__ dist2,
    const int* __restrict__ len1, const int* __restrict__ len2,
    const float* __restrict__ bw,
    const float* __restrict__ Wa, const float* __restrict__ ba,
    const float* __restrict__ Wdb, const float* __restrict__ bdb)
{
    extern __shared__ float sm[];
    uint32_t* sAb = (uint32_t*)sm;       // 4 x 1792 u32 = 7168 floats
    float* sWng = sm + 7168;             // 101 rows x stride 132 = 13332 (row0 = wn)
    float* sWa  = sWng + 13332;          // 256
    float* sBw  = sWa + 256;             // 128
    float* sDist= sBw + 128;             // 104
    float* sRaw = sDist + 104;           // 104
    float* sAtt = sRaw + 104;            // 104
    float* sC   = sAtt + 104;            // 8
    float* sDot = sC + 8;                // 2
    float* sPart= sDot + 2;              // 256
    __shared__ int sIdx;
    // 21462 floats = 85848 B

    const int tid  = threadIdx.x;
    const int warp = tid >> 5, lane = tid & 31;
    const int gid  = lane >> 2, tig = lane & 3;

    sWa[tid] = Wa[tid];
    if (tid < 128) sBw[tid] = bw[tid];
    __syncthreads();
    if (warp == 0) {
        float s0 = 0.f, s1 = 0.f;
#pragma unroll
        for (int q = 0; q < 4; ++q) {
            s0 += sBw[lane + 32 * q] * sWa[lane + 32 * q];
            s1 += sBw[lane + 32 * q] * sWa[128 + lane + 32 * q];
        }
#pragma unroll
        for (int o = 16; o > 0; o >>= 1) {
            s0 += __shfl_xor_sync(0xffffffffu, s0, o);
            s1 += __shfl_xor_sync(0xffffffffu, s1, o);
        }
        if (lane == 0) { sDot[0] = s0; sDot[1] = s1; }
    }

    const float bav = ba[0], wdbv = Wdb[0], bdbv = bdb[0];

    while (true) {
        __syncthreads();
        if (tid == 0) sIdx = (int)atomicAdd(&g_counter, 1u);
        __syncthreads();
        const int item = sIdx;
        if (item >= 2 * BATCH) break;
        const int b = item >> 1, side = item & 1;

        const float* node  = side ? node2  : node1;
        const float* neigh = side ? neigh2 : neigh1;
        const float* dist  = side ? dist2  : dist1;
        int len = side ? len2[b] : len1[b];
        if (len < 1) len = 1; if (len > NMAXN) len = NMAXN;
        const int M = len + 1;
        const int mcount = (M + 15) >> 4;

        if (tid < NMAXN) { sDist[tid] = dist[(size_t)b * NMAXN + tid]; sRaw[tid] = 0.f; }
        if (tid == 128) sC[0] = 0.f;

        const float* nodeRow   = node  + (size_t)b * HD;
        const float* neighBase = neigh + (size_t)b * NMAXN * HD;

        // L2 prefetch of the whole item (neigh block is contiguous)
        {
            const char* pnb = (const char*)neighBase;
            const int pbytes = len * (HD * 4);
            for (int off = tid * 128; off < pbytes; off += 256 * 128) pref_l2(pnb + off);
            if (tid < 24) pref_l2((const char*)nodeRow + tid * 128);
        }

        int nact = 0;
        const float* srcp[4];
        int sbase[4];
#pragma unroll
        for (int i = 0; i < 4; ++i) {
            int f = tid + i * 256;
            if (f < M * 8) {
                int r = f >> 3, j = f & 7;
                int mt = r >> 4, r16 = r & 15, g8 = r16 & 7, hib = r16 >> 3;
                int ks = j >> 2, half = (j >> 1) & 1, tg = (j & 1) * 2;
                srcp[i]  = (r == 0 ? nodeRow : neighBase + (size_t)(r - 1) * HD) + j * 4;
                sbase[i] = ((mt * 2 + ks) * 32 + g8 * 4 + tg) * 4 + half * 2 + hib;
                nact = i + 1;
            }
        }

        float acc[7][2][4];
#pragma unroll
        for (int mt = 0; mt < 7; ++mt)
#pragma unroll
            for (int ni = 0; ni < 2; ++ni)
#pragma unroll
                for (int q = 0; q < 4; ++q) acc[mt][ni][q] = 0.f;

        // ---- prologue: commit kt 0 and kt 1, preload kt 2 ----
        float4 v[4];
#pragma unroll
        for (int i = 0; i < 4; ++i) if (i < nact) v[i] = *(const float4*)(srcp[i]);
#pragma unroll
        for (int i = 0; i < 4; ++i) {
            if (i < nact) {
                sAb[sbase[i]]     = pack_bf2(v[i].x, v[i].y);
                sAb[sbase[i] + 4] = pack_bf2(v[i].z, v[i].w);
            }
        }
#pragma unroll
        for (int i = 0; i < 4; ++i)
            if (i < nact) v[i] = *(const float4*)(srcp[i] + 32);
#pragma unroll
        for (int i = 0; i < 4; ++i) {
            if (i < nact) {
                sAb[1792 + sbase[i]]     = pack_bf2(v[i].x, v[i].y);
                sAb[1792 + sbase[i] + 4] = pack_bf2(v[i].z, v[i].w);
            }
        }
#pragma unroll
        for (int i = 0; i < 4; ++i)
            if (i < nact) v[i] = *(const float4*)(srcp[i] + 64);
        __syncthreads();

        // ---- mainloop: 12 iterations, 2 k-tiles each, 1 barrier each ----
        for (int it = 0; it < 12; ++it) {
            const int k0 = 2 * it;
            const uint32_t* cur0 = sAb + ((k0)     & 3) * 1792;
            const uint32_t* cur1 = sAb + ((k0 + 1) & 3) * 1792;

            // commit A(k0+2) (loaded last iteration), start load of A(k0+3)
            if (it < 11) {
                uint32_t* nxt = sAb + ((k0 + 2) & 3) * 1792;
#pragma unroll
                for (int i = 0; i < 4; ++i) {
                    if (i < nact) {
                        nxt[sbase[i]]     = pack_bf2(v[i].x, v[i].y);
                        nxt[sbase[i] + 4] = pack_bf2(v[i].z, v[i].w);
                    }
                }
#pragma unroll
                for (int i = 0; i < 4; ++i)
                    if (i < nact) v[i] = *(const float4*)(srcp[i] + (k0 + 3) * 32);
            }

            // B fragments for both k-tiles (L1-hot after first item)
            uint4 bqa0 = *(const uint4*)(g_WfragB + ((k0 * 16 + 2 * warp)     * 32 + lane) * 4);
            uint4 bqa1 = *(const uint4*)(g_WfragB + ((k0 * 16 + 2 * warp + 1) * 32 + lane) * 4);
            uint4 bqb0 = *(const uint4*)(g_WfragB + (((k0 + 1) * 16 + 2 * warp)     * 32 + lane) * 4);
            uint4 bqb1 = *(const uint4*)(g_WfragB + (((k0 + 1) * 16 + 2 * warp + 1) * 32 + lane) * 4);

            const uint32_t* pa0 = (const uint32_t*)&bqa0;
            const uint32_t* pa1 = (const uint32_t*)&bqa1;
#pragma unroll
            for (int ks = 0; ks < 2; ++ks) {
#pragma unroll
                for (int mt = 0; mt < 7; ++mt) {
                    if (mt >= mcount) break;
                    uint4 av = *(const uint4*)(cur0 + ((mt * 2 + ks) * 32 + lane) * 4);
                    const uint32_t* a = (const uint32_t*)&av;
                    mma_bf16(acc[mt][0], a, pa0[2 * ks], pa0[2 * ks + 1]);
                    mma_bf16(acc[mt][1], a, pa1[2 * ks], pa1[2 * ks + 1]);
                }
            }
            const uint32_t* pb0 = (const uint32_t*)&bqb0;
            const uint32_t* pb1 = (const uint32_t*)&bqb1;
#pragma unroll
            for (int ks = 0; ks < 2; ++ks) {
#pragma unroll
                for (int mt = 0; mt < 7; ++mt) {
                    if (mt >= mcount) break;
                    uint4 av = *(const uint4*)(cur1 + ((mt * 2 + ks) * 32 + lane) * 4);
                    const uint32_t* a = (const uint32_t*)&av;
                    mma_bf16(acc[mt][0], a, pb0[2 * ks], pb0[2 * ks + 1]);
                    mma_bf16(acc[mt][1], a, pb1[2 * ks], pb1[2 * ks + 1]);
                }
            }

            // commit A(k0+3) (its load overlapped the MMA phase), preload A(k0+4)
            if (it < 11) {
                uint32_t* nxt2 = sAb + ((k0 + 3) & 3) * 1792;
#pragma unroll
                for (int i = 0; i < 4; ++i) {
                    if (i < nact) {
                        nxt2[sbase[i]]     = pack_bf2(v[i].x, v[i].y);
                        nxt2[sbase[i] + 4] = pack_bf2(v[i].z, v[i].w);
                    }
                }
                if (it < 10) {
#pragma unroll
                    for (int i = 0; i < 4; ++i)
                        if (i < nact) v[i] = *(const float4*)(srcp[i] + (k0 + 4) * 32);
                }
            }
            __syncthreads();
        }

        // epilogue: + bw -> sWng scatter, AND fused attention dots via atomics
#pragma unroll
        for (int mt = 0; mt < 7; ++mt) {
            if (mt >= mcount) break;
            int r0 = mt * 16 + gid, r1 = r0 + 8;
            float pr0 = 0.f, pr1 = 0.f;
#pragma unroll
            for (int ni = 0; ni < 2; ++ni) {
                int cc = (2 * warp + ni) * 8 + tig * 2;
                float wa0n = sWa[128 + cc], wa1n = sWa[128 + cc + 1];
                if (r0 < M) {
                    float2 o = { acc[mt][ni][0] + sBw[cc], acc[mt][ni][1] + sBw[cc + 1] };
                    *(float2*)(sWng + r0 * 132 + cc) = o;
                    if (r0 == 0)
                        pr0 += acc[mt][ni][0] * sWa[cc] + acc[mt][ni][1] * sWa[cc + 1];
                    else
                        pr0 += acc[mt][ni][0] * wa0n + acc[mt][ni][1] * wa1n;
                }
                if (r1 < M) {
                    float2 o = { acc[mt][ni][2] + sBw[cc], acc[mt][ni][3] + sBw[cc + 1] };
                    *(float2*)(sWng + r1 * 132 + cc) = o;
                    pr1 += acc[mt][ni][2] * wa0n + acc[mt][ni][3] * wa1n;
                }
            }
            pr0 += __shfl_xor_sync(0xffffffffu, pr0, 1);
            pr0 += __shfl_xor_sync(0xffffffffu, pr0, 2);
            pr1 += __shfl_xor_sync(0xffffffffu, pr1, 1);
            pr1 += __shfl_xor_sync(0xffffffffu, pr1, 2);
            if (tig == 0) {
                if (r0 < M) {
                    if (r0 == 0) atomicAdd(sC, pr0);
                    else         atomicAdd(&sRaw[r0 - 1], pr0);
                }
                if (r1 < M) atomicAdd(&sRaw[r1 - 1], pr1);
            }
        }
        __syncthreads();

        // warp 0: leaky_relu + dist bias, masked softmax
        if (warp == 0) {
            float cst = sC[0] + sDot[0] + sDot[1] + bav;
            float sc[4], ev[4];
            float mx = -3.4e38f;
#pragma unroll
            for (int q = 0; q < 4; ++q) {
                int n = lane + 32 * q;
                float vv = -3.4e38f;
                if (n < len) {
                    float x = cst + sRaw[n];
                    x = (x > 0.f) ? x : 0.01f * x;
                    vv = x + sDist[n] * wdbv + bdbv;
                }
                sc[q] = vv; mx = fmaxf(mx, vv);
            }
#pragma unroll
            for (int o = 16; o > 0; o >>= 1) mx = fmaxf(mx, __shfl_xor_sync(0xffffffffu, mx, o));
            float s = 0.f;
#pragma unroll
            for (int q = 0; q < 4; ++q) {
                int n = lane + 32 * q;
                float e = (n < len) ? expf(sc[q] - mx) : 0.f;
                ev[q] = e; s += e;
            }
#pragma unroll
            for (int o = 16; o > 0; o >>= 1) s += __shfl_xor_sync(0xffffffffu, s, o);
            float inv = 1.f / s;
#pragma unroll
            for (int q = 0; q < 4; ++q) {
                int n = lane + 32 * q;
                if (n < NMAXN) sAtt[n] = ev[q] * inv;
            }
        }
        __syncthreads();

        // ctx: split n-range across both thread halves (all 8 warps active)
        {
            const int col = tid & 127, half = tid >> 7;
            const int nmid = len >> 1;
            const int n0 = half ? nmid : 0;
            const int n1 = half ? len : nmid;
            float c0 = 0.f, c1 = 0.f;
            int n = n0;
            for (; n + 1 < n1; n += 2) {
                c0 += sAtt[n]     * sWng[(n + 1) * 132 + col];
                c1 += sAtt[n + 1] * sWng[(n + 2) * 132 + col];
            }
            if (n < n1) c0 += sAtt[n] * sWng[(n + 1) * 132 + col];
            sPart[tid] = c0 + c1;
        }
        __syncthreads();
        if (tid < 128) {
            float ctx = sPart[tid] + sPart[tid + 128];
            g_sim[(size_t)b * 256 + side * 128 + tid] = ctx * sWng[tid];
        }
    }
}

// ---------------------------------------------------------------------------
// xneigh_mm: g_h[:,896:1152] = relu(g_sim) @ Wn + bn   bf16 MMA
// grid (64,4), block 256
// ---------------------------------------------------------------------------
__global__ void __launch_bounds__(256) xneigh_mm_kernel(const float* __restrict__ bn)
{
    __shared__ uint32_t sAb[8 * 256];

    const int tid  = threadIdx.x;
    const int warp = tid >> 5, lane = tid & 31;
    const int gid  = lane >> 2, tig = lane & 3;
    const int m0   = blockIdx.x * 16;
    const int ntg  = blockIdx.y * 8 + warp;

    const bool active = tid < 128;
    if (active) {
        int r = tid >> 3, j = tid & 7;
        int g8 = (r & 15) & 7, hib = (r & 15) >> 3;
        int ks = j >> 2, half = (j >> 1) & 1, tg = (j & 1) * 2;
        const float* srcp = g_sim + (size_t)(m0 + r) * 256 + j * 4;
        int sbase = (ks * 32 + g8 * 4 + tg) * 4 + half * 2 + hib;
#pragma unroll
        for (int kt = 0; kt < 8; ++kt) {
            float4 t = *(const float4*)(srcp + kt * 32);
            t.x = fmaxf(t.x, 0.f); t.y = fmaxf(t.y, 0.f);
            t.z = fmaxf(t.z, 0.f); t.w = fmaxf(t.w, 0.f);
            sAb[kt * 256 + sbase]     = pack_bf2(t.x, t.y);
            sAb[kt * 256 + sbase + 4] = pack_bf2(t.z, t.w);
        }
    }
    __syncthreads();

    float acc[4];
#pragma unroll
    for (int q = 0; q < 4; ++q) acc[q] = 0.f;

#pragma unroll
    for (int kt = 0; kt < 8; ++kt) {
        uint4 bq = *(const uint4*)(g_WnfragB + ((kt * 32 + ntg) * 32 + lane) * 4);
        const uint32_t* p = (const uint32_t*)&bq;
        const uint32_t* cur = sAb + kt * 256;
#pragma unroll
        for (int ks = 0; ks < 2; ++ks) {
            uint4 av = *(const uint4*)(cur + (ks * 32 + lane) * 4);
            mma_bf16(acc, (const uint32_t*)&av, p[2 * ks], p[2 * ks + 1]);
        }
    }

    const int cc = ntg * 8 + tig * 2;
    const float bv0 = bn[cc], bv1 = bn[cc + 1];
    {
        int r0 = m0 + gid, r1 = r0 + 8;
        g_h[(size_t)r0 * 1152 + 896 + cc]     = acc[0] + bv0;
        g_h[(size_t)r0 * 1152 + 896 + cc + 1] = acc[1] + bv1;
        g_h[(size_t)r1 * 1152 + 896 + cc]     = acc[2] + bv0;
        g_h[(size_t)r1 * 1152 + 896 + cc + 1] = acc[3] + bv1;
    }
}

// ---------------------------------------------------------------------------
// head_mm: g_h1 = gelu(g_h @ W1 + b1)  bf16, grid (64,9) = 16x64 tiles
// 8-buffer ring, 4 k-tiles per barrier (9 barriers)
// ---------------------------------------------------------------------------
__global__ void __launch_bounds__(256) head_mm_kernel(const float* __restrict__ b1)
{
    __shared__ uint32_t sAb[8 * 256];

    const int tid  = threadIdx.x;
    const int warp = tid >> 5, lane = tid & 31;
    const int gid  = lane >> 2, tig = lane & 3;
    const int m0   = blockIdx.x * 16;
    const int ntg  = blockIdx.y * 8 + warp;

    {
        const char* ph = (const char*)(g_h + (size_t)m0 * 1152);
        for (int off = tid * 128; off < 16 * 1152 * 4; off += 256 * 128) pref_l2(ph + off);
    }

    const bool active = tid < 128;
    const float* srcp = g_h;
    int sbase = 0;
    if (active) {
        int r = tid >> 3, j = tid & 7;
        int g8 = (r & 15) & 7, hib = (r & 15) >> 3;
        int ks = j >> 2, half = (j >> 1) & 1, tg = (j & 1) * 2;
        srcp  = g_h + (size_t)(m0 + r) * 1152 + j * 4;
        sbase = (ks * 32 + g8 * 4 + tg) * 4 + half * 2 + hib;
    }

    float acc[4];
#pragma unroll
    for (int q = 0; q < 4; ++q) acc[q] = 0.f;

    float4 v[4];
#pragma unroll
    for (int j = 0; j < 4; ++j) v[j] = make_float4(0.f, 0.f, 0.f, 0.f);
    if (active) {
#pragma unroll
        for (int j = 0; j < 4; ++j) {
            float4 t = *(const float4*)(srcp + j * 32);
            sAb[j * 256 + sbase]     = pack_bf2(t.x, t.y);
            sAb[j * 256 + sbase + 4] = pack_bf2(t.z, t.w);
        }
#pragma unroll
        for (int j = 0; j < 4; ++j) v[j] = *(const float4*)(srcp + (4 + j) * 32);
    }
    __syncthreads();

    for (int it = 0; it < 9; ++it) {
        const int kt0 = it * 4;
        const int g   = (it & 1) * 4;

        uint4 bq[4];
#pragma unroll
        for (int j = 0; j < 4; ++j)
            bq[j] = *(const uint4*)(g_W1fragB + (((kt0 + j) * 72 + ntg) * 32 + lane) * 4);

        if (it < 8 && active) {
            const int go = ((it + 1) & 1) * 4;
#pragma unroll
            for (int j = 0; j < 4; ++j) {
                sAb[(go + j) * 256 + sbase]     = pack_bf2(v[j].x, v[j].y);
                sAb[(go + j) * 256 + sbase + 4] = pack_bf2(v[j].z, v[j].w);
            }
            if (it < 7) {
#pragma unroll
                for (int j = 0; j < 4; ++j)
                    v[j] = *(const float4*)(srcp + (kt0 + 8 + j) * 32);
            }
        }

#pragma unroll
        for (int j = 0; j < 4; ++j) {
            const uint32_t* cur = sAb + (g + j) * 256;
            const uint32_t* p = (const uint32_t*)&bq[j];
#pragma unroll
            for (int ks = 0; ks < 2; ++ks) {
                uint4 av = *(const uint4*)(cur + (ks * 32 + lane) * 4);
                mma_bf16(acc, (const uint32_t*)&av, p[2 * ks], p[2 * ks + 1]);
            }
        }
        __syncthreads();
    }

    const int cc = ntg * 8 + tig * 2;
    const float bv0 = b1[cc], bv1 = b1[cc + 1];
    {
        int r0 = m0 + gid, r1 = r0 + 8;
        float x;
        x = acc[0] + bv0; g_h1[(size_t)r0 * 576 + cc]     = x * normcdff(x);
        x = acc[1] + bv1; g_h1[(size_t)r0 * 576 + cc + 1] = x * normcdff(x);
        x = acc[2] + bv0; g_h1[(size_t)r1 * 576 + cc]     = x * normcdff(x);
        x = acc[3] + bv1; g_h1[(size_t)r1 * 576 + cc + 1] = x * normcdff(x);
    }
}

// ---------------------------------------------------------------------------
// logits: out = log_softmax(g_h1 @ W2 + b2)   grid 128, block 256
// ---------------------------------------------------------------------------
__global__ void logits_kernel(const float* __restrict__ W2, const float* __restrict__ b2,
                              float* __restrict__ out)
{
    __shared__ float sW2[1152];
    const int tid = threadIdx.x;
    const int lane = tid & 31, warp = tid >> 5;
    for (int j = tid; j < 1152; j += 256) sW2[j] = W2[j];
    __syncthreads();

    const int r = blockIdx.x * 8 + warp;
    float p0 = 0.f, p1 = 0.f;
    const float* hrow = g_h1 + (size_t)r * 576;
#pragma unroll
    for (int q = 0; q < 18; ++q) {
        int j = lane + 32 * q;
        float h = hrow[j];
        p0 += h * sW2[2 * j];
        p1 += h * sW2[2 * j + 1];
    }
#pragma unroll
    for (int o = 16; o > 0; o >>= 1) {
        p0 += __shfl_xor_sync(0xffffffffu, p0, o);
        p1 += __shfl_xor_sync(0xffffffffu, p1, o);
    }
    if (lane == 0) {
        float l0 = p0 + b2[0], l1 = p1 + b2[1];
        float m = fmaxf(l0, l1);
        float lse = m + logf(expf(l0 - m) + expf(l1 - m));
        out[(size_t)r * 2 + 0] = l0 - lse;
        out[(size_t)r * 2 + 1] = l1 - lse;
    }
}

// ---------------------------------------------------------------------------
extern "C" void kernel_launch(void* const* d_in, const int* in_sizes, int n_in,
                              void* d_out, int out_size)
{
    const float* pooled = (const float*)d_in[0];
    const float* x_coord= (const float*)d_in[1];
    const float* node1  = (const float*)d_in[2];
    const float* node2  = (const float*)d_in[3];
    const float* neigh1 = (const float*)d_in[4];
    const float* neigh2 = (const float*)d_in[5];
    const float* dist1  = (const float*)d_in[6];
    const float* dist2  = (const float*)d_in[7];
    const int*   len1   = (const int*)d_in[8];
    const int*   len2   = (const int*)d_in[9];
    const float* Ww  = (const float*)d_in[10];
    const float* bw  = (const float*)d_in[11];
    const float* Wa  = (const float*)d_in[12];
    const float* ba  = (const float*)d_in[13];
    const float* Wdb = (const float*)d_in[14];
    const float* bdb = (const float*)d_in[15];
    const float* Wn  = (const float*)d_in[16];
    const float* bn  = (const float*)d_in[17];
    const float* Wc  = (const float*)d_in[18];
    const float* bc  = (const float*)d_in[19];
    const float* W1  = (const float*)d_in[20];
    const float* b1  = (const float*)d_in[21];
    const float* W2  = (const float*)d_in[22];
    const float* b2  = (const float*)d_in[23];
    float* out = (float*)d_out;

    prep_kernel<<<5200, 256>>>(Ww, W1, Wn, pooled, x_coord, Wc, bc);

    const int smB = 21464 * (int)sizeof(float);   // 85856 B
    cudaFuncSetAttribute(side_kernel, cudaFuncAttributeMaxDynamicSharedMemorySize, smB);
    side_kernel<<<296, 256, smB>>>(node1, node2, neigh1, neigh2,
                                   dist1, dist2, len1, len2,
                                   bw, Wa, ba, Wdb, bdb);

    xneigh_mm_kernel<<<dim3(64, 4), 256>>>(bn);

    head_mm_kernel<<<dim3(64, 9), 256>>>(b1);

    logits_kernel<<<BATCH / 8, 256>>>(W2, b2, out);
}